// round 2
// baseline (speedup 1.0000x reference)
#include <cuda_runtime.h>
#include <math.h>

#define B_   4
#define S_   4096
#define E_   2048
#define NH_  16
#define HD_  128
#define MTOT (B_ * S_)       /* 16384 */
#define NHEADS (B_ * NH_)    /* 64 */

// ---------------- scratch (device globals; no runtime allocation) ----------------
__device__ float g_q   [(size_t)MTOT * E_];
__device__ float g_k   [(size_t)MTOT * E_];
__device__ float g_v   [(size_t)MTOT * E_];
__device__ float g_attn[(size_t)MTOT * E_];
__device__ float g_kk  [NHEADS * HD_ * HD_];
__device__ float g_ktv [NHEADS * HD_ * HD_];
__device__ float g_score[NHEADS * HD_ * HD_];

// =================================================================================
// Core 128x128 tile GEMM: C_tile(128x128) = A_tile(128xK, row stride lda)
//                                         @ B_tile(Kx128, row stride ldb)
// 256 threads, 8x8 accumulators per thread, BK=16, float4 smem traffic.
// =================================================================================
__device__ __forceinline__ void gemm_core(const float* __restrict__ A, int lda,
                                          const float* __restrict__ B, int ldb,
                                          int K, int tid, float acc[8][8])
{
    __shared__ float As[16][132];   // As[k][m], padded to keep float4 reads aligned
    __shared__ float Bs[16][128];   // Bs[k][n]

    const int tx = tid & 15;
    const int ty = tid >> 4;
    const int ar = tid >> 2;            // 0..63
    const int ac = (tid & 3) << 2;      // 0,4,8,12
    const int br = tid >> 5;            // 0..7
    const int bc = (tid & 31) << 2;     // 0..124

    for (int k0 = 0; k0 < K; k0 += 16) {
        float4 a0 = *(const float4*)(A + (size_t)ar        * lda + k0 + ac);
        float4 a1 = *(const float4*)(A + (size_t)(ar + 64) * lda + k0 + ac);
        float4 b0 = *(const float4*)(B + (size_t)(k0 + br)     * ldb + bc);
        float4 b1 = *(const float4*)(B + (size_t)(k0 + br + 8) * ldb + bc);

        __syncthreads();   // protect previous iteration's compute
        As[ac + 0][ar] = a0.x; As[ac + 1][ar] = a0.y;
        As[ac + 2][ar] = a0.z; As[ac + 3][ar] = a0.w;
        As[ac + 0][ar + 64] = a1.x; As[ac + 1][ar + 64] = a1.y;
        As[ac + 2][ar + 64] = a1.z; As[ac + 3][ar + 64] = a1.w;
        *(float4*)&Bs[br][bc]     = b0;
        *(float4*)&Bs[br + 8][bc] = b1;
        __syncthreads();

        #pragma unroll
        for (int kk = 0; kk < 16; kk++) {
            float ra[8], rb[8];
            *(float4*)&ra[0] = *(const float4*)&As[kk][ty * 4];
            *(float4*)&ra[4] = *(const float4*)&As[kk][64 + ty * 4];
            *(float4*)&rb[0] = *(const float4*)&Bs[kk][tx * 4];
            *(float4*)&rb[4] = *(const float4*)&Bs[kk][64 + tx * 4];
            #pragma unroll
            for (int i = 0; i < 8; i++)
                #pragma unroll
                for (int j = 0; j < 8; j++)
                    acc[i][j] = fmaf(ra[i], rb[j], acc[i][j]);
        }
    }
}

// ---------------------------------------------------------------------------------
// Full-matrix GEMM + bias: C[M x N] = A[M x K] @ W[K x N] + bias
// grid = (N/128, M/128), block = 256
// ---------------------------------------------------------------------------------
__global__ __launch_bounds__(256) void gemm_bias_kernel(
    const float* __restrict__ A, const float* __restrict__ W,
    const float* __restrict__ bias, float* __restrict__ C, int K, int N)
{
    const int tid = threadIdx.x;
    const float* Ab = A + (size_t)blockIdx.y * 128 * K;
    const float* Wb = W + blockIdx.x * 128;
    float* Cb = C + (size_t)blockIdx.y * 128 * N + blockIdx.x * 128;
    const float* bb = bias + blockIdx.x * 128;

    float acc[8][8];
    #pragma unroll
    for (int i = 0; i < 8; i++)
        #pragma unroll
        for (int j = 0; j < 8; j++) acc[i][j] = 0.f;

    gemm_core(Ab, K, Wb, N, K, tid, acc);

    const int tx = tid & 15, ty = tid >> 4;
    float bv0[4], bv1[4];
    #pragma unroll
    for (int j = 0; j < 4; j++) { bv0[j] = bb[tx * 4 + j]; bv1[j] = bb[64 + tx * 4 + j]; }

    #pragma unroll
    for (int i = 0; i < 8; i++) {
        int r = (i < 4) ? (ty * 4 + i) : (64 + ty * 4 + i - 4);
        float4 o0 = make_float4(acc[i][0] + bv0[0], acc[i][1] + bv0[1],
                                acc[i][2] + bv0[2], acc[i][3] + bv0[3]);
        float4 o1 = make_float4(acc[i][4] + bv1[0], acc[i][5] + bv1[1],
                                acc[i][6] + bv1[2], acc[i][7] + bv1[3]);
        *(float4*)(Cb + (size_t)r * N + tx * 4)      = o0;
        *(float4*)(Cb + (size_t)r * N + 64 + tx * 4) = o1;
    }
}

// ---------------------------------------------------------------------------------
// Zero the K^T K / K^T V accumulators (graph replays must re-zero)
// ---------------------------------------------------------------------------------
__global__ void zero_kernel()
{
    int i = blockIdx.x * 256 + threadIdx.x;
    if (i < NHEADS * HD_ * HD_) { g_kk[i] = 0.f; g_ktv[i] = 0.f; }
}

// ---------------------------------------------------------------------------------
// K^T K and K^T V per head, S chunked by 512, atomic accumulation.
// grid = (64 heads, 8 chunks, 2 which), block = 256
// Output C[d][e] = sum_s K[s][d] * X[s][e]   (X = K or V)
// ---------------------------------------------------------------------------------
__global__ __launch_bounds__(256) void ktk_kernel()
{
    const int head = blockIdx.x, chunk = blockIdx.y, which = blockIdx.z;
    const int b = head >> 4, h = head & 15;
    const size_t base = ((size_t)(b * S_) + (size_t)chunk * 512) * E_ + h * HD_;
    const float* Kp = g_k + base;
    const float* Xp = (which ? g_v : g_k) + base;
    float* out = (which ? g_ktv : g_kk) + (size_t)head * HD_ * HD_;

    __shared__ float As[16][132];   // As[s][d]
    __shared__ float Bs[16][128];   // Bs[s][e]
    const int tid = threadIdx.x;
    const int tx = tid & 15, ty = tid >> 4;
    const int br = tid >> 5;            // 0..7
    const int bc = (tid & 31) << 2;     // 0..124

    float acc[8][8];
    #pragma unroll
    for (int i = 0; i < 8; i++)
        #pragma unroll
        for (int j = 0; j < 8; j++) acc[i][j] = 0.f;

    for (int k0 = 0; k0 < 512; k0 += 16) {
        float4 a0 = *(const float4*)(Kp + (size_t)(k0 + br)     * E_ + bc);
        float4 a1 = *(const float4*)(Kp + (size_t)(k0 + br + 8) * E_ + bc);
        float4 b0 = *(const float4*)(Xp + (size_t)(k0 + br)     * E_ + bc);
        float4 b1 = *(const float4*)(Xp + (size_t)(k0 + br + 8) * E_ + bc);

        __syncthreads();
        *(float4*)&As[br][bc]     = a0;
        *(float4*)&As[br + 8][bc] = a1;
        *(float4*)&Bs[br][bc]     = b0;
        *(float4*)&Bs[br + 8][bc] = b1;
        __syncthreads();

        #pragma unroll
        for (int kk = 0; kk < 16; kk++) {
            float ra[8], rb[8];
            *(float4*)&ra[0] = *(const float4*)&As[kk][ty * 4];
            *(float4*)&ra[4] = *(const float4*)&As[kk][64 + ty * 4];
            *(float4*)&rb[0] = *(const float4*)&Bs[kk][tx * 4];
            *(float4*)&rb[4] = *(const float4*)&Bs[kk][64 + tx * 4];
            #pragma unroll
            for (int i = 0; i < 8; i++)
                #pragma unroll
                for (int j = 0; j < 8; j++)
                    acc[i][j] = fmaf(ra[i], rb[j], acc[i][j]);
        }
    }

    #pragma unroll
    for (int i = 0; i < 8; i++) {
        int r = (i < 4) ? (ty * 4 + i) : (64 + ty * 4 + i - 4);
        #pragma unroll
        for (int j = 0; j < 8; j++) {
            int c = (j < 4) ? (tx * 4 + j) : (64 + tx * 4 + j - 4);
            atomicAdd(out + r * HD_ + c, acc[i][j]);
        }
    }
}

// ---------------------------------------------------------------------------------
// Per head: solve (alpha I + K^T K) X = K^T V by Gauss-Jordan (SPD, no pivoting),
// then row-softmax(X) -> g_score.  64 blocks x 256 threads, 128KB dynamic smem.
// Column-owner scheme: thread `tid` owns augmented column `tid` (0..255).
// ---------------------------------------------------------------------------------
#define LDAUG 257
__global__ __launch_bounds__(256) void solve_softmax_kernel(const float* __restrict__ alpha)
{
    extern __shared__ float sAug[];        // [128][LDAUG]
    __shared__ float facs[128];
    const int head = blockIdx.x;
    const int tid = threadIdx.x;
    const float* kk  = g_kk  + (size_t)head * HD_ * HD_;
    const float* ktv = g_ktv + (size_t)head * HD_ * HD_;
    const float a = alpha[0];

    for (int idx = tid; idx < HD_ * HD_; idx += 256) {
        int r = idx >> 7, c = idx & 127;
        sAug[r * LDAUG + c]        = kk[idx] + (r == c ? a : 0.f);
        sAug[r * LDAUG + 128 + c]  = ktv[idx];
    }
    __syncthreads();

    for (int k = 0; k < HD_; k++) {
        if (tid < 128) facs[tid] = sAug[tid * LDAUG + k];
        __syncthreads();
        float pivc = sAug[k * LDAUG + tid] / facs[k];
        sAug[k * LDAUG + tid] = pivc;
        __syncthreads();
        #pragma unroll 4
        for (int r = 0; r < HD_; r++) {
            if (r != k) sAug[r * LDAUG + tid] -= facs[r] * pivc;
        }
        __syncthreads();
    }

    // Row softmax of X (columns 128..255)
    const int warp = tid >> 5, lane = tid & 31;
    for (int r = warp; r < HD_; r += 8) {
        float vals[4];
        float mx = -1e30f;
        #pragma unroll
        for (int t = 0; t < 4; t++) {
            vals[t] = sAug[r * LDAUG + 128 + lane + 32 * t];
            mx = fmaxf(mx, vals[t]);
        }
        #pragma unroll
        for (int o = 16; o; o >>= 1) mx = fmaxf(mx, __shfl_xor_sync(0xffffffffu, mx, o));
        float sum = 0.f;
        #pragma unroll
        for (int t = 0; t < 4; t++) { vals[t] = expf(vals[t] - mx); sum += vals[t]; }
        #pragma unroll
        for (int o = 16; o; o >>= 1) sum += __shfl_xor_sync(0xffffffffu, sum, o);
        float inv = 1.f / sum;
        #pragma unroll
        for (int t = 0; t < 4; t++)
            g_score[(size_t)head * HD_ * HD_ + r * HD_ + lane + 32 * t] = vals[t] * inv;
    }
}

// ---------------------------------------------------------------------------------
// out[s][e] = sum_d q[s][d] * score[d][e] per head.  grid = (64, S/128)
// ---------------------------------------------------------------------------------
__global__ __launch_bounds__(256) void attn_gemm_kernel()
{
    const int head = blockIdx.x, stile = blockIdx.y;
    const int b = head >> 4, h = head & 15;
    const int tid = threadIdx.x;
    const size_t base = ((size_t)(b * S_) + (size_t)stile * 128) * E_ + h * HD_;
    const float* A  = g_q + base;
    const float* Bm = g_score + (size_t)head * HD_ * HD_;
    float* C = g_attn + base;

    float acc[8][8];
    #pragma unroll
    for (int i = 0; i < 8; i++)
        #pragma unroll
        for (int j = 0; j < 8; j++) acc[i][j] = 0.f;

    gemm_core(A, E_, Bm, HD_, HD_, tid, acc);

    const int tx = tid & 15, ty = tid >> 4;
    #pragma unroll
    for (int i = 0; i < 8; i++) {
        int r = (i < 4) ? (ty * 4 + i) : (64 + ty * 4 + i - 4);
        *(float4*)(C + (size_t)r * E_ + tx * 4)      = *(float4*)&acc[i][0];
        *(float4*)(C + (size_t)r * E_ + 64 + tx * 4) = *(float4*)&acc[i][4];
    }
}

// =================================================================================
extern "C" void kernel_launch(void* const* d_in, const int* in_sizes, int n_in,
                              void* d_out, int out_size)
{
    (void)in_sizes; (void)n_in; (void)out_size;
    const float* x     = (const float*)d_in[0];
    const float* alpha = (const float*)d_in[1];
    const float* Wq    = (const float*)d_in[2];
    const float* bq    = (const float*)d_in[3];
    const float* Wk    = (const float*)d_in[4];
    const float* bk    = (const float*)d_in[5];
    const float* Wv    = (const float*)d_in[6];
    const float* bv    = (const float*)d_in[7];
    const float* Wfc   = (const float*)d_in[8];
    const float* bfc   = (const float*)d_in[9];
    float* out = (float*)d_out;

    float *q, *k, *v, *attn;
    cudaGetSymbolAddress((void**)&q,    g_q);
    cudaGetSymbolAddress((void**)&k,    g_k);
    cudaGetSymbolAddress((void**)&v,    g_v);
    cudaGetSymbolAddress((void**)&attn, g_attn);

    const int smem_solve = 128 * LDAUG * sizeof(float);
    cudaFuncSetAttribute(solve_softmax_kernel,
                         cudaFuncAttributeMaxDynamicSharedMemorySize, smem_solve);

    dim3 gGemm(E_ / 128, MTOT / 128);   // (16, 128)

    zero_kernel<<<(NHEADS * HD_ * HD_ + 255) / 256, 256>>>();

    gemm_bias_kernel<<<gGemm, 256>>>(x, Wq, bq, q, E_, E_);
    gemm_bias_kernel<<<gGemm, 256>>>(x, Wk, bk, k, E_, E_);
    gemm_bias_kernel<<<gGemm, 256>>>(x, Wv, bv, v, E_, E_);

    ktk_kernel<<<dim3(NHEADS, S_ / 512, 2), 256>>>();

    solve_softmax_kernel<<<NHEADS, 256, smem_solve>>>(alpha);

    attn_gemm_kernel<<<dim3(NHEADS, S_ / 128), 256>>>();

    gemm_bias_kernel<<<gGemm, 256>>>(attn, Wfc, bfc, out, E_, E_);
}

// round 4
// speedup vs baseline: 1.9305x; 1.9305x over previous
#include <cuda_runtime.h>
#include <cuda_bf16.h>
#include <math.h>
#include <stdint.h>

#define B_   4
#define S_   4096
#define E_   2048
#define NH_  16
#define HD_  128
#define MTOT (B_ * S_)       /* 16384 */
#define NHEADS (B_ * NH_)    /* 64 */

typedef __nv_bfloat16 bf16;

// ---------------- scratch (device globals; no runtime allocation) ----------------
__device__ bf16  g_xh [(size_t)MTOT * E_], g_xl [(size_t)MTOT * E_];
__device__ bf16  g_wqh[(size_t)E_ * E_],   g_wql[(size_t)E_ * E_];
__device__ bf16  g_wkh[(size_t)E_ * E_],   g_wkl[(size_t)E_ * E_];
__device__ bf16  g_wvh[(size_t)E_ * E_],   g_wvl[(size_t)E_ * E_];
__device__ bf16  g_wfh[(size_t)E_ * E_],   g_wfl[(size_t)E_ * E_];
__device__ bf16  g_qh [(size_t)MTOT * E_], g_ql [(size_t)MTOT * E_];
__device__ float g_k  [(size_t)MTOT * E_], g_v  [(size_t)MTOT * E_];
__device__ bf16  g_Kth[(size_t)NHEADS * HD_ * S_], g_Ktl[(size_t)NHEADS * HD_ * S_];
__device__ bf16  g_Vth[(size_t)NHEADS * HD_ * S_], g_Vtl[(size_t)NHEADS * HD_ * S_];
__device__ float g_kk [NHEADS * HD_ * HD_], g_ktv[NHEADS * HD_ * HD_];
__device__ bf16  g_sTh[NHEADS * HD_ * HD_], g_sTl[NHEADS * HD_ * HD_];
__device__ bf16  g_ah [(size_t)MTOT * E_], g_al [(size_t)MTOT * E_];

// =========================== helpers ==============================================
__device__ __forceinline__ uint32_t smem_u32(const void* p) {
    return (uint32_t)__cvta_generic_to_shared(p);
}
__device__ __forceinline__ void split1(float v, bf16& h, bf16& l) {
    h = __float2bfloat16(v);
    l = __float2bfloat16(v - __bfloat162float(h));
}
__device__ __forceinline__ uint32_t pack2(bf16 a, bf16 b) {
    return (uint32_t)__bfloat16_as_ushort(a) | ((uint32_t)__bfloat16_as_ushort(b) << 16);
}

#define CP_COMMIT() asm volatile("cp.async.commit_group;" ::: "memory")
#define CP_WAIT(n)  asm volatile("cp.async.wait_group %0;" :: "n"(n) : "memory")

__device__ __forceinline__ void cpa16(uint32_t s, const void* g) {
    asm volatile("cp.async.cg.shared.global [%0], [%1], 16;" :: "r"(s), "l"(g));
}
__device__ __forceinline__ void ldsm4(uint32_t (&r)[4], uint32_t a) {
    asm volatile("ldmatrix.sync.aligned.m8n8.x4.shared.b16 {%0,%1,%2,%3}, [%4];"
                 : "=r"(r[0]), "=r"(r[1]), "=r"(r[2]), "=r"(r[3]) : "r"(a));
}
__device__ __forceinline__ void mma_bf16(float (&c)[4], const uint32_t (&a)[4],
                                         uint32_t b0, uint32_t b1) {
    asm volatile("mma.sync.aligned.m16n8k16.row.col.f32.bf16.bf16.f32 "
        "{%0,%1,%2,%3}, {%4,%5,%6,%7}, {%8,%9}, {%0,%1,%2,%3};"
        : "+f"(c[0]), "+f"(c[1]), "+f"(c[2]), "+f"(c[3])
        : "r"(a[0]), "r"(a[1]), "r"(a[2]), "r"(a[3]), "r"(b0), "r"(b1));
}

// =========================== mma GEMM machinery ===================================
// Block tile 128x128x32, 8 warps (2 M x 4 N), warp tile 64x32.
// smem tile: 128 rows x 32 bf16, rows padded to 40 halfs (80B) -> conflict-free
// ldmatrix (row stride 20 banks; 8 rows cover all 32 banks).
#define TILE_BYTES 10240            /* 128 * 80 */
#define STAGE_BYTES (4 * TILE_BYTES)

// load a 128x32 bf16 tile (global row stride ldg halves) into padded smem
__device__ __forceinline__ void load_tile_p(uint32_t sbase, const bf16* g, int ldg, int tid) {
    #pragma unroll
    for (int t = 0; t < 2; t++) {
        int idx = tid + t * 256;        // 512 chunks of 16B
        int r = idx >> 2, c = idx & 3;
        cpa16(sbase + r * 80 + c * 16, g + (size_t)r * ldg + c * 8);
    }
}
__device__ __forceinline__ void stage_load(uint32_t sbase,
    const bf16* Ah, const bf16* Al, int lda,
    const bf16* Bh, const bf16* Bl, int ldb, int tid)
{
    load_tile_p(sbase,                  Ah, lda, tid);
    load_tile_p(sbase + TILE_BYTES,     Al, lda, tid);
    load_tile_p(sbase + 2 * TILE_BYTES, Bh, ldb, tid);
    load_tile_p(sbase + 3 * TILE_BYTES, Bl, ldb, tid);
}

// consume one 128x128x32 stage: 3 chains (AhBh, AhBl, AlBh)
__device__ __forceinline__ void compute_stage(uint32_t sbase, int wm, int wn, int lane,
                                              float (&acc)[4][4][4])
{
    const uint32_t sAh = sbase;
    const uint32_t sAl = sbase + TILE_BYTES;
    const uint32_t sBh = sbase + 2 * TILE_BYTES;
    const uint32_t sBl = sbase + 3 * TILE_BYTES;
    const int arow = wm * 64 + (lane & 15);
    const int acolx = (lane & 16) ? 8 : 0;
    const int brow = wn * 32 + (lane & 7) + ((lane & 16) ? 8 : 0);
    const int bcolx = (lane & 8) ? 8 : 0;

    #pragma unroll
    for (int kk = 0; kk < 2; kk++) {
        const int acol = kk * 16 + acolx;
        const int bcol = kk * 16 + bcolx;
        uint32_t ah[4][4], al[4][4], bh[2][4], bl[2][4];
        #pragma unroll
        for (int mi = 0; mi < 4; mi++) {
            ldsm4(ah[mi], sAh + (arow + mi * 16) * 80 + acol * 2);
            ldsm4(al[mi], sAl + (arow + mi * 16) * 80 + acol * 2);
        }
        #pragma unroll
        for (int nj2 = 0; nj2 < 2; nj2++) {
            ldsm4(bh[nj2], sBh + (brow + nj2 * 16) * 80 + bcol * 2);
            ldsm4(bl[nj2], sBl + (brow + nj2 * 16) * 80 + bcol * 2);
        }
        #pragma unroll
        for (int mi = 0; mi < 4; mi++)
            #pragma unroll
            for (int nj = 0; nj < 4; nj++) {
                const int j2 = nj >> 1, jo = (nj & 1) * 2;
                mma_bf16(acc[mi][nj], ah[mi], bh[j2][jo], bh[j2][jo + 1]);
                mma_bf16(acc[mi][nj], ah[mi], bl[j2][jo], bl[j2][jo + 1]);
                mma_bf16(acc[mi][nj], al[mi], bh[j2][jo], bh[j2][jo + 1]);
            }
    }
}

// full pipelined mainloop over KT k-tiles of 32 (KT >= 2)
__device__ __forceinline__ void run_mainloop(uint32_t sm,
    const bf16* pAh, const bf16* pAl, int lda,
    const bf16* pBh, const bf16* pBl, int ldb, int KT,
    int wm, int wn, int lane, int tid, float (&acc)[4][4][4])
{
    stage_load(sm, pAh, pAl, lda, pBh, pBl, ldb, tid);
    CP_COMMIT();
    stage_load(sm + STAGE_BYTES, pAh + 32, pAl + 32, lda, pBh + 32, pBl + 32, ldb, tid);
    CP_COMMIT();
    for (int i = 0; i < KT; i++) {
        if (i + 2 < KT) { CP_WAIT(1); } else { CP_WAIT(0); }
        __syncthreads();
        if (i + 2 < KT) {
            const int k0 = (i + 2) * 32, slot = (i + 2) % 3;
            stage_load(sm + slot * STAGE_BYTES, pAh + k0, pAl + k0, lda,
                       pBh + k0, pBl + k0, ldb, tid);
            CP_COMMIT();
        }
        compute_stage(sm + (i % 3) * STAGE_BYTES, wm, wn, lane, acc);
    }
}

// =========================== conversion kernels ===================================
__global__ void conv_split_kernel(const float* __restrict__ in, bf16* __restrict__ hi,
                                  bf16* __restrict__ lo) {
    size_t i = ((size_t)blockIdx.x * 256 + threadIdx.x) * 4;
    float4 v = *(const float4*)(in + i);
    bf16 h0, l0, h1, l1, h2, l2, h3, l3;
    split1(v.x, h0, l0); split1(v.y, h1, l1); split1(v.z, h2, l2); split1(v.w, h3, l3);
    *(uint2*)(hi + i) = make_uint2(pack2(h0, h1), pack2(h2, h3));
    *(uint2*)(lo + i) = make_uint2(pack2(l0, l1), pack2(l2, l3));
}

// W[K x N] fp32 -> Wt[N x K] bf16 hi/lo (transpose + split)
__global__ void conv_splitT_kernel(const float* __restrict__ W, bf16* __restrict__ th,
                                   bf16* __restrict__ tl) {
    __shared__ float t[32][33];
    const int n0 = blockIdx.x * 32, k0 = blockIdx.y * 32;
    const int tx = threadIdx.x, ty = threadIdx.y;
    #pragma unroll
    for (int j = 0; j < 4; j++)
        t[ty + 8 * j][tx] = W[(size_t)(k0 + ty + 8 * j) * E_ + n0 + tx];
    __syncthreads();
    #pragma unroll
    for (int j = 0; j < 4; j++) {
        int n = n0 + ty + 8 * j;
        float v = t[tx][ty + 8 * j];
        bf16 h, l; split1(v, h, l);
        th[(size_t)n * E_ + k0 + tx] = h;
        tl[(size_t)n * E_ + k0 + tx] = l;
    }
}

// k/v fp32 [B*S x E] -> Kt[b*E + e][s] bf16 hi/lo (transpose + split), row stride S_
__global__ void transpose_split_kv_kernel(const float* __restrict__ src, bf16* __restrict__ th,
                                          bf16* __restrict__ tl) {
    __shared__ float t[32][33];
    const int s0 = blockIdx.x * 32, e0 = blockIdx.y * 32, b = blockIdx.z;
    const int tx = threadIdx.x, ty = threadIdx.y;
    #pragma unroll
    for (int j = 0; j < 4; j++)
        t[ty + 8 * j][tx] = src[(size_t)(b * S_ + s0 + ty + 8 * j) * E_ + e0 + tx];
    __syncthreads();
    #pragma unroll
    for (int j = 0; j < 4; j++) {
        int e = e0 + ty + 8 * j;
        float v = t[tx][ty + 8 * j];
        bf16 h, l; split1(v, h, l);
        size_t row = (size_t)b * E_ + e;
        th[row * S_ + s0 + tx] = h;
        tl[row * S_ + s0 + tx] = l;
    }
}

// =========================== big GEMM kernel ======================================
// C[M x 2048] = (Ah+Al) @ (Bh+Bl)^T + bias ; B stored [N x K] row-major.
// grid (16, M/128). outF!=null: fp32 out; else bf16 hi/lo (outH/outL).
__global__ __launch_bounds__(256, 1) void gemm_big(
    const bf16* __restrict__ Ah, const bf16* __restrict__ Al,
    const bf16* __restrict__ Bh, const bf16* __restrict__ Bl,
    const float* __restrict__ bias, float* __restrict__ outF,
    bf16* __restrict__ outH, bf16* __restrict__ outL)
{
    extern __shared__ char smraw[];
    const uint32_t sm = (smem_u32(smraw) + 127) & ~127u;
    const int tid = threadIdx.x, lane = tid & 31, wid = tid >> 5;
    const int wm = wid >> 2, wn = wid & 3;
    const int m0 = blockIdx.y * 128, n0 = blockIdx.x * 128;

    float acc[4][4][4];
    #pragma unroll
    for (int a = 0; a < 4; a++)
        #pragma unroll
        for (int b = 0; b < 4; b++)
            #pragma unroll
            for (int c = 0; c < 4; c++) acc[a][b][c] = 0.f;

    run_mainloop(sm, Ah + (size_t)m0 * E_, Al + (size_t)m0 * E_, E_,
                 Bh + (size_t)n0 * E_, Bl + (size_t)n0 * E_, E_, E_ / 32,
                 wm, wn, lane, tid, acc);

    const int row_base = m0 + wm * 64 + (lane >> 2);
    const int col_base = n0 + wn * 32 + (lane & 3) * 2;
    #pragma unroll
    for (int mi = 0; mi < 4; mi++)
        #pragma unroll
        for (int nj = 0; nj < 4; nj++) {
            const int r = row_base + mi * 16;
            const int c = col_base + nj * 8;
            const float b0 = bias[c], b1 = bias[c + 1];
            float v00 = acc[mi][nj][0] + b0, v01 = acc[mi][nj][1] + b1;
            float v10 = acc[mi][nj][2] + b0, v11 = acc[mi][nj][3] + b1;
            if (outF) {
                *(float2*)(outF + (size_t)r * E_ + c)       = make_float2(v00, v01);
                *(float2*)(outF + (size_t)(r + 8) * E_ + c) = make_float2(v10, v11);
            } else {
                bf16 h0, l0, h1, l1;
                split1(v00, h0, l0); split1(v01, h1, l1);
                *(uint32_t*)(outH + (size_t)r * E_ + c) = pack2(h0, h1);
                *(uint32_t*)(outL + (size_t)r * E_ + c) = pack2(l0, l1);
                split1(v10, h0, l0); split1(v11, h1, l1);
                *(uint32_t*)(outH + (size_t)(r + 8) * E_ + c) = pack2(h0, h1);
                *(uint32_t*)(outL + (size_t)(r + 8) * E_ + c) = pack2(l0, l1);
            }
        }
}

// =========================== K^T K / K^T V ========================================
// grid (64 heads, 2): which=0 -> KK, which=1 -> KTV. M=N=128, K=4096.
__global__ __launch_bounds__(256, 1) void ktk_mma()
{
    extern __shared__ char smraw[];
    const uint32_t sm = (smem_u32(smraw) + 127) & ~127u;
    const int tid = threadIdx.x, lane = tid & 31, wid = tid >> 5;
    const int wm = wid >> 2, wn = wid & 3;
    const int head = blockIdx.x, which = blockIdx.y;

    const size_t hb = (size_t)head * HD_ * S_;
    const bf16* pAh = g_Kth + hb;
    const bf16* pAl = g_Ktl + hb;
    const bf16* pBh = (which ? g_Vth : g_Kth) + hb;
    const bf16* pBl = (which ? g_Vtl : g_Ktl) + hb;
    float* out = (which ? g_ktv : g_kk) + (size_t)head * HD_ * HD_;

    float acc[4][4][4];
    #pragma unroll
    for (int a = 0; a < 4; a++)
        #pragma unroll
        for (int b = 0; b < 4; b++)
            #pragma unroll
            for (int c = 0; c < 4; c++) acc[a][b][c] = 0.f;

    run_mainloop(sm, pAh, pAl, S_, pBh, pBl, S_, S_ / 32, wm, wn, lane, tid, acc);

    const int row_base = wm * 64 + (lane >> 2);
    const int col_base = wn * 32 + (lane & 3) * 2;
    #pragma unroll
    for (int mi = 0; mi < 4; mi++)
        #pragma unroll
        for (int nj = 0; nj < 4; nj++) {
            const int r = row_base + mi * 16;
            const int c = col_base + nj * 8;
            *(float2*)(out + (size_t)r * HD_ + c) =
                make_float2(acc[mi][nj][0], acc[mi][nj][1]);
            *(float2*)(out + (size_t)(r + 8) * HD_ + c) =
                make_float2(acc[mi][nj][2], acc[mi][nj][3]);
        }
}

// =========================== solve + softmax (fp32 SIMT) ==========================
#define LDAUG 257
__global__ __launch_bounds__(256) void solve_softmax_kernel(const float* __restrict__ alpha)
{
    extern __shared__ float sAug[];        // [128][LDAUG]
    __shared__ float facs[128];
    const int head = blockIdx.x;
    const int tid = threadIdx.x;
    const float* kk  = g_kk  + (size_t)head * HD_ * HD_;
    const float* ktv = g_ktv + (size_t)head * HD_ * HD_;
    const float a = alpha[0];

    for (int idx = tid; idx < HD_ * HD_; idx += 256) {
        int r = idx >> 7, c = idx & 127;
        sAug[r * LDAUG + c]       = kk[idx] + (r == c ? a : 0.f);
        sAug[r * LDAUG + 128 + c] = ktv[idx];
    }
    __syncthreads();

    for (int k = 0; k < HD_; k++) {
        if (tid < 128) facs[tid] = sAug[tid * LDAUG + k];
        __syncthreads();
        float pivc = sAug[k * LDAUG + tid] / facs[k];
        sAug[k * LDAUG + tid] = pivc;
        __syncthreads();
        #pragma unroll 4
        for (int r = 0; r < HD_; r++)
            if (r != k) sAug[r * LDAUG + tid] -= facs[r] * pivc;
        __syncthreads();
    }

    const int warp = tid >> 5, lane = tid & 31;
    for (int r = warp; r < HD_; r += 8) {
        float vals[4];
        float mx = -1e30f;
        #pragma unroll
        for (int t = 0; t < 4; t++) {
            vals[t] = sAug[r * LDAUG + 128 + lane + 32 * t];
            mx = fmaxf(mx, vals[t]);
        }
        #pragma unroll
        for (int o = 16; o; o >>= 1) mx = fmaxf(mx, __shfl_xor_sync(0xffffffffu, mx, o));
        float sum = 0.f;
        #pragma unroll
        for (int t = 0; t < 4; t++) { vals[t] = expf(vals[t] - mx); sum += vals[t]; }
        #pragma unroll
        for (int o = 16; o; o >>= 1) sum += __shfl_xor_sync(0xffffffffu, sum, o);
        float inv = 1.f / sum;
        #pragma unroll
        for (int t = 0; t < 4; t++) {
            int e = lane + 32 * t;
            float p = vals[t] * inv;
            bf16 h, l; split1(p, h, l);
            g_sTh[(size_t)head * HD_ * HD_ + e * HD_ + r] = h;  // score^T[e][d=r]
            g_sTl[(size_t)head * HD_ * HD_ + e * HD_ + r] = l;
        }
    }
}

// =========================== attn = Q @ score =====================================
// grid (64 heads, 32 s-tiles): D[s(128)][e(128)] = sum_d q[s][d] * scoreT[e][d]; K=128.
__global__ __launch_bounds__(256, 1) void attn_mma()
{
    extern __shared__ char smraw[];
    const uint32_t sm = (smem_u32(smraw) + 127) & ~127u;
    const int tid = threadIdx.x, lane = tid & 31, wid = tid >> 5;
    const int wm = wid >> 2, wn = wid & 3;
    const int head = blockIdx.x, stile = blockIdx.y;
    const int bb = head >> 4, h = head & 15;
    const size_t arow0 = (size_t)(bb * S_ + stile * 128);

    const bf16* pAh = g_qh + arow0 * E_ + h * 128;
    const bf16* pAl = g_ql + arow0 * E_ + h * 128;
    const bf16* pBh = g_sTh + (size_t)head * HD_ * HD_;
    const bf16* pBl = g_sTl + (size_t)head * HD_ * HD_;

    float acc[4][4][4];
    #pragma unroll
    for (int a = 0; a < 4; a++)
        #pragma unroll
        for (int b = 0; b < 4; b++)
            #pragma unroll
            for (int c = 0; c < 4; c++) acc[a][b][c] = 0.f;

    run_mainloop(sm, pAh, pAl, E_, pBh, pBl, HD_, HD_ / 32, wm, wn, lane, tid, acc);

    const int row_base = wm * 64 + (lane >> 2);
    const int col_base = h * 128 + wn * 32 + (lane & 3) * 2;
    #pragma unroll
    for (int mi = 0; mi < 4; mi++)
        #pragma unroll
        for (int nj = 0; nj < 4; nj++) {
            const size_t r = arow0 + row_base + mi * 16;
            const int c = col_base + nj * 8;
            bf16 h0, l0, h1, l1;
            split1(acc[mi][nj][0], h0, l0); split1(acc[mi][nj][1], h1, l1);
            *(uint32_t*)(g_ah + r * E_ + c) = pack2(h0, h1);
            *(uint32_t*)(g_al + r * E_ + c) = pack2(l0, l1);
            split1(acc[mi][nj][2], h0, l0); split1(acc[mi][nj][3], h1, l1);
            *(uint32_t*)(g_ah + (r + 8) * E_ + c) = pack2(h0, h1);
            *(uint32_t*)(g_al + (r + 8) * E_ + c) = pack2(l0, l1);
        }
}

// =================================================================================
extern "C" void kernel_launch(void* const* d_in, const int* in_sizes, int n_in,
                              void* d_out, int out_size)
{
    (void)in_sizes; (void)n_in; (void)out_size;
    const float* x     = (const float*)d_in[0];
    const float* alpha = (const float*)d_in[1];
    const float* Wq    = (const float*)d_in[2];
    const float* bq    = (const float*)d_in[3];
    const float* Wk    = (const float*)d_in[4];
    const float* bk    = (const float*)d_in[5];
    const float* Wv    = (const float*)d_in[6];
    const float* bv    = (const float*)d_in[7];
    const float* Wfc   = (const float*)d_in[8];
    const float* bfc   = (const float*)d_in[9];
    float* out = (float*)d_out;

    bf16 *xh, *xl, *wqh, *wql, *wkh, *wkl, *wvh, *wvl, *wfh, *wfl, *qh, *ql, *ah, *al;
    float *k, *v;
    cudaGetSymbolAddress((void**)&xh, g_xh);   cudaGetSymbolAddress((void**)&xl, g_xl);
    cudaGetSymbolAddress((void**)&wqh, g_wqh); cudaGetSymbolAddress((void**)&wql, g_wql);
    cudaGetSymbolAddress((void**)&wkh, g_wkh); cudaGetSymbolAddress((void**)&wkl, g_wkl);
    cudaGetSymbolAddress((void**)&wvh, g_wvh); cudaGetSymbolAddress((void**)&wvl, g_wvl);
    cudaGetSymbolAddress((void**)&wfh, g_wfh); cudaGetSymbolAddress((void**)&wfl, g_wfl);
    cudaGetSymbolAddress((void**)&qh, g_qh);   cudaGetSymbolAddress((void**)&ql, g_ql);
    cudaGetSymbolAddress((void**)&k, g_k);     cudaGetSymbolAddress((void**)&v, g_v);
    cudaGetSymbolAddress((void**)&ah, g_ah);   cudaGetSymbolAddress((void**)&al, g_al);

    const int SMEM_MMA = 3 * STAGE_BYTES + 128;   // 123008
    const int SMEM_S   = 128 * LDAUG * 4;         // 131584
    cudaFuncSetAttribute(gemm_big, cudaFuncAttributeMaxDynamicSharedMemorySize, SMEM_MMA);
    cudaFuncSetAttribute(ktk_mma,  cudaFuncAttributeMaxDynamicSharedMemorySize, SMEM_MMA);
    cudaFuncSetAttribute(attn_mma, cudaFuncAttributeMaxDynamicSharedMemorySize, SMEM_MMA);
    cudaFuncSetAttribute(solve_softmax_kernel, cudaFuncAttributeMaxDynamicSharedMemorySize, SMEM_S);

    // 1) split x into bf16 hi/lo
    conv_split_kernel<<<(int)((size_t)MTOT * E_ / 4 / 256), 256>>>(x, xh, xl);
    // 2) transpose+split weights -> [N x K] hi/lo
    dim3 tb(32, 8), tg(E_ / 32, E_ / 32);
    conv_splitT_kernel<<<tg, tb>>>(Wq, wqh, wql);
    conv_splitT_kernel<<<tg, tb>>>(Wk, wkh, wkl);
    conv_splitT_kernel<<<tg, tb>>>(Wv, wvh, wvl);
    conv_splitT_kernel<<<tg, tb>>>(Wfc, wfh, wfl);
    // 3) Q/K/V projections
    dim3 gg(E_ / 128, MTOT / 128);   // (16, 128)
    gemm_big<<<gg, 256, SMEM_MMA>>>(xh, xl, wqh, wql, bq, nullptr, qh, ql);
    gemm_big<<<gg, 256, SMEM_MMA>>>(xh, xl, wkh, wkl, bk, k, nullptr, nullptr);
    gemm_big<<<gg, 256, SMEM_MMA>>>(xh, xl, wvh, wvl, bv, v, nullptr, nullptr);
    // 4) transpose+split K, V to [head*HD + d][s]
    bf16 *Kth, *Ktl, *Vth, *Vtl;
    cudaGetSymbolAddress((void**)&Kth, g_Kth); cudaGetSymbolAddress((void**)&Ktl, g_Ktl);
    cudaGetSymbolAddress((void**)&Vth, g_Vth); cudaGetSymbolAddress((void**)&Vtl, g_Vtl);
    dim3 kg(S_ / 32, E_ / 32, B_);
    transpose_split_kv_kernel<<<kg, tb>>>(k, Kth, Ktl);
    transpose_split_kv_kernel<<<kg, tb>>>(v, Vth, Vtl);
    // 5) K^T K and K^T V
    ktk_mma<<<dim3(NHEADS, 2), 256, SMEM_MMA>>>();
    // 6) solve + softmax -> score^T (bf16 hi/lo)
    solve_softmax_kernel<<<NHEADS, 256, SMEM_S>>>(alpha);
    // 7) attn = Q @ score
    attn_mma<<<dim3(NHEADS, S_ / 128), 256, SMEM_MMA>>>();
    // 8) output projection
    gemm_big<<<gg, 256, SMEM_MMA>>>(ah, al, wfh, wfl, bfc, out, nullptr, nullptr);
}

// round 5
// speedup vs baseline: 2.5348x; 1.3130x over previous
#include <cuda_runtime.h>
#include <cuda_bf16.h>
#include <math.h>
#include <stdint.h>

#define B_   4
#define S_   4096
#define E_   2048
#define NH_  16
#define HD_  128
#define MTOT (B_ * S_)       /* 16384 */
#define NHEADS (B_ * NH_)    /* 64 */

typedef __nv_bfloat16 bf16;

// ---------------- scratch (device globals; no runtime allocation) ----------------
__device__ bf16  g_xh [(size_t)MTOT * E_], g_xl [(size_t)MTOT * E_];
__device__ bf16  g_wqh[(size_t)E_ * E_],   g_wql[(size_t)E_ * E_];
__device__ bf16  g_wkh[(size_t)E_ * E_],   g_wkl[(size_t)E_ * E_];
__device__ bf16  g_wvh[(size_t)E_ * E_],   g_wvl[(size_t)E_ * E_];
__device__ bf16  g_wfh[(size_t)E_ * E_],   g_wfl[(size_t)E_ * E_];
__device__ bf16  g_qh [(size_t)MTOT * E_], g_ql [(size_t)MTOT * E_];
__device__ float g_k  [(size_t)MTOT * E_], g_v  [(size_t)MTOT * E_];
__device__ bf16  g_Kth[(size_t)NHEADS * HD_ * S_], g_Ktl[(size_t)NHEADS * HD_ * S_];
__device__ bf16  g_Vth[(size_t)NHEADS * HD_ * S_], g_Vtl[(size_t)NHEADS * HD_ * S_];
__device__ float g_kk [NHEADS * HD_ * HD_], g_ktv[NHEADS * HD_ * HD_];
__device__ bf16  g_sTh[NHEADS * HD_ * HD_], g_sTl[NHEADS * HD_ * HD_];
__device__ bf16  g_ah [(size_t)MTOT * E_], g_al [(size_t)MTOT * E_];

// =========================== helpers ==============================================
__device__ __forceinline__ uint32_t smem_u32(const void* p) {
    return (uint32_t)__cvta_generic_to_shared(p);
}
__device__ __forceinline__ void split1(float v, bf16& h, bf16& l) {
    h = __float2bfloat16(v);
    l = __float2bfloat16(v - __bfloat162float(h));
}
__device__ __forceinline__ uint32_t pack2(bf16 a, bf16 b) {
    return (uint32_t)__bfloat16_as_ushort(a) | ((uint32_t)__bfloat16_as_ushort(b) << 16);
}

#define CP_COMMIT() asm volatile("cp.async.commit_group;" ::: "memory")
#define CP_WAIT(n)  asm volatile("cp.async.wait_group %0;" :: "n"(n) : "memory")

__device__ __forceinline__ void cpa16(uint32_t s, const void* g) {
    asm volatile("cp.async.cg.shared.global [%0], [%1], 16;" :: "r"(s), "l"(g));
}
__device__ __forceinline__ void ldsm4(uint32_t (&r)[4], uint32_t a) {
    asm volatile("ldmatrix.sync.aligned.m8n8.x4.shared.b16 {%0,%1,%2,%3}, [%4];"
                 : "=r"(r[0]), "=r"(r[1]), "=r"(r[2]), "=r"(r[3]) : "r"(a));
}
__device__ __forceinline__ void mma_bf16(float (&c)[4], const uint32_t (&a)[4],
                                         uint32_t b0, uint32_t b1) {
    asm volatile("mma.sync.aligned.m16n8k16.row.col.f32.bf16.bf16.f32 "
        "{%0,%1,%2,%3}, {%4,%5,%6,%7}, {%8,%9}, {%0,%1,%2,%3};"
        : "+f"(c[0]), "+f"(c[1]), "+f"(c[2]), "+f"(c[3])
        : "r"(a[0]), "r"(a[1]), "r"(a[2]), "r"(a[3]), "r"(b0), "r"(b1));
}

// =========================== mma GEMM machinery ===================================
// Block tile 128x128x64, 8 warps (2 M x 4 N), warp tile 64x32.
// smem tile: 128 rows x 64 bf16 = 128B rows, SW128 XOR-swizzled (conflict-free).
#define TILE_BYTES 16384            /* 128 * 128B */
#define STAGE_BYTES (4 * TILE_BYTES) /* Ah | Al | Bh | Bl = 64KB */

__device__ __forceinline__ uint32_t swz(uint32_t row, uint32_t cb) {
    return row * 128 + (cb ^ ((row & 7) << 4));
}

// load a 128x64 bf16 tile (global row stride ldg halves) into swizzled smem
__device__ __forceinline__ void load_tile64(uint32_t sbase, const bf16* g, int ldg, int tid) {
    #pragma unroll
    for (int t = 0; t < 4; t++) {
        int idx = tid + t * 256;        // 1024 chunks of 16B
        int r = idx >> 3, c = idx & 7;
        cpa16(sbase + swz(r, c * 16), g + (size_t)r * ldg + c * 8);
    }
}
__device__ __forceinline__ void stage_load(uint32_t sbase,
    const bf16* Ah, const bf16* Al, int lda,
    const bf16* Bh, const bf16* Bl, int ldb, int tid)
{
    load_tile64(sbase,                  Ah, lda, tid);
    load_tile64(sbase + TILE_BYTES,     Al, lda, tid);
    load_tile64(sbase + 2 * TILE_BYTES, Bh, ldb, tid);
    load_tile64(sbase + 3 * TILE_BYTES, Bl, ldb, tid);
}

// consume one 128x128x64 stage: 3 chains (AhBh, AhBl, AlBh)
__device__ __forceinline__ void compute_stage(uint32_t sbase, int wm, int wn, int lane,
                                              float (&acc)[4][4][4])
{
    const uint32_t sAh = sbase;
    const uint32_t sAl = sbase + TILE_BYTES;
    const uint32_t sBh = sbase + 2 * TILE_BYTES;
    const uint32_t sBl = sbase + 3 * TILE_BYTES;
    const int arow = wm * 64 + (lane & 15);
    const uint32_t acbx = (lane & 16) ? 16 : 0;     // byte offset within k-group
    const int brow = wn * 32 + (lane & 7) + ((lane & 16) ? 8 : 0);
    const uint32_t bcbx = (lane & 8) ? 16 : 0;

    #pragma unroll
    for (int kk = 0; kk < 4; kk++) {
        const uint32_t acb = kk * 32 + acbx;
        const uint32_t bcb = kk * 32 + bcbx;
        uint32_t ah[4][4], al[4][4], bh[2][4], bl[2][4];
        #pragma unroll
        for (int mi = 0; mi < 4; mi++) {
            ldsm4(ah[mi], sAh + swz(arow + mi * 16, acb));
            ldsm4(al[mi], sAl + swz(arow + mi * 16, acb));
        }
        #pragma unroll
        for (int nj2 = 0; nj2 < 2; nj2++) {
            ldsm4(bh[nj2], sBh + swz(brow + nj2 * 16, bcb));
            ldsm4(bl[nj2], sBl + swz(brow + nj2 * 16, bcb));
        }
        #pragma unroll
        for (int mi = 0; mi < 4; mi++)
            #pragma unroll
            for (int nj = 0; nj < 4; nj++) {
                const int j2 = nj >> 1, jo = (nj & 1) * 2;
                mma_bf16(acc[mi][nj], ah[mi], bh[j2][jo], bh[j2][jo + 1]);
                mma_bf16(acc[mi][nj], ah[mi], bl[j2][jo], bl[j2][jo + 1]);
                mma_bf16(acc[mi][nj], al[mi], bh[j2][jo], bh[j2][jo + 1]);
            }
    }
}

// full pipelined mainloop over KT k-tiles of 64 (KT >= 2), 3-stage (192KB)
__device__ __forceinline__ void run_mainloop(uint32_t sm,
    const bf16* pAh, const bf16* pAl, int lda,
    const bf16* pBh, const bf16* pBl, int ldb, int KT,
    int wm, int wn, int lane, int tid, float (&acc)[4][4][4])
{
    stage_load(sm, pAh, pAl, lda, pBh, pBl, ldb, tid);
    CP_COMMIT();
    stage_load(sm + STAGE_BYTES, pAh + 64, pAl + 64, lda, pBh + 64, pBl + 64, ldb, tid);
    CP_COMMIT();
    for (int i = 0; i < KT; i++) {
        if (i + 2 < KT) { CP_WAIT(1); } else { CP_WAIT(0); }
        __syncthreads();
        if (i + 2 < KT) {
            const int k0 = (i + 2) * 64, slot = (i + 2) % 3;
            stage_load(sm + slot * STAGE_BYTES, pAh + k0, pAl + k0, lda,
                       pBh + k0, pBl + k0, ldb, tid);
            CP_COMMIT();
        }
        compute_stage(sm + (i % 3) * STAGE_BYTES, wm, wn, lane, acc);
    }
}

// =========================== conversion kernels ===================================
__global__ void conv_split_kernel(const float* __restrict__ in, bf16* __restrict__ hi,
                                  bf16* __restrict__ lo) {
    size_t i = ((size_t)blockIdx.x * 256 + threadIdx.x) * 4;
    float4 v = *(const float4*)(in + i);
    bf16 h0, l0, h1, l1, h2, l2, h3, l3;
    split1(v.x, h0, l0); split1(v.y, h1, l1); split1(v.z, h2, l2); split1(v.w, h3, l3);
    *(uint2*)(hi + i) = make_uint2(pack2(h0, h1), pack2(h2, h3));
    *(uint2*)(lo + i) = make_uint2(pack2(l0, l1), pack2(l2, l3));
}

// W[K x N] fp32 -> Wt[N x K] bf16 hi/lo (transpose + split)
__global__ void conv_splitT_kernel(const float* __restrict__ W, bf16* __restrict__ th,
                                   bf16* __restrict__ tl) {
    __shared__ float t[32][33];
    const int n0 = blockIdx.x * 32, k0 = blockIdx.y * 32;
    const int tx = threadIdx.x, ty = threadIdx.y;
    #pragma unroll
    for (int j = 0; j < 4; j++)
        t[ty + 8 * j][tx] = W[(size_t)(k0 + ty + 8 * j) * E_ + n0 + tx];
    __syncthreads();
    #pragma unroll
    for (int j = 0; j < 4; j++) {
        int n = n0 + ty + 8 * j;
        float v = t[tx][ty + 8 * j];
        bf16 h, l; split1(v, h, l);
        th[(size_t)n * E_ + k0 + tx] = h;
        tl[(size_t)n * E_ + k0 + tx] = l;
    }
}

// k/v fp32 [B*S x E] -> Kt[b*E + e][s] bf16 hi/lo (transpose + split), row stride S_
__global__ void transpose_split_kv_kernel(const float* __restrict__ src, bf16* __restrict__ th,
                                          bf16* __restrict__ tl) {
    __shared__ float t[32][33];
    const int s0 = blockIdx.x * 32, e0 = blockIdx.y * 32, b = blockIdx.z;
    const int tx = threadIdx.x, ty = threadIdx.y;
    #pragma unroll
    for (int j = 0; j < 4; j++)
        t[ty + 8 * j][tx] = src[(size_t)(b * S_ + s0 + ty + 8 * j) * E_ + e0 + tx];
    __syncthreads();
    #pragma unroll
    for (int j = 0; j < 4; j++) {
        int e = e0 + ty + 8 * j;
        float v = t[tx][ty + 8 * j];
        bf16 h, l; split1(v, h, l);
        size_t row = (size_t)b * E_ + e;
        th[row * S_ + s0 + tx] = h;
        tl[row * S_ + s0 + tx] = l;
    }
}

// =========================== big GEMM kernel ======================================
// C[M x 2048] = (Ah+Al) @ (Bh+Bl)^T + bias ; B stored [N x K] row-major.
// grid (16, M/128). outF!=null: fp32 out; else bf16 hi/lo (outH/outL).
__global__ __launch_bounds__(256, 1) void gemm_big(
    const bf16* __restrict__ Ah, const bf16* __restrict__ Al,
    const bf16* __restrict__ Bh, const bf16* __restrict__ Bl,
    const float* __restrict__ bias, float* __restrict__ outF,
    bf16* __restrict__ outH, bf16* __restrict__ outL)
{
    extern __shared__ char smraw[];
    const uint32_t sm = (smem_u32(smraw) + 127) & ~127u;
    const int tid = threadIdx.x, lane = tid & 31, wid = tid >> 5;
    const int wm = wid >> 2, wn = wid & 3;
    const int m0 = blockIdx.y * 128, n0 = blockIdx.x * 128;

    float acc[4][4][4];
    #pragma unroll
    for (int a = 0; a < 4; a++)
        #pragma unroll
        for (int b = 0; b < 4; b++)
            #pragma unroll
            for (int c = 0; c < 4; c++) acc[a][b][c] = 0.f;

    run_mainloop(sm, Ah + (size_t)m0 * E_, Al + (size_t)m0 * E_, E_,
                 Bh + (size_t)n0 * E_, Bl + (size_t)n0 * E_, E_, E_ / 64,
                 wm, wn, lane, tid, acc);

    const int row_base = m0 + wm * 64 + (lane >> 2);
    const int col_base = n0 + wn * 32 + (lane & 3) * 2;
    #pragma unroll
    for (int mi = 0; mi < 4; mi++)
        #pragma unroll
        for (int nj = 0; nj < 4; nj++) {
            const int r = row_base + mi * 16;
            const int c = col_base + nj * 8;
            const float b0 = bias[c], b1 = bias[c + 1];
            float v00 = acc[mi][nj][0] + b0, v01 = acc[mi][nj][1] + b1;
            float v10 = acc[mi][nj][2] + b0, v11 = acc[mi][nj][3] + b1;
            if (outF) {
                *(float2*)(outF + (size_t)r * E_ + c)       = make_float2(v00, v01);
                *(float2*)(outF + (size_t)(r + 8) * E_ + c) = make_float2(v10, v11);
            } else {
                bf16 h0, l0, h1, l1;
                split1(v00, h0, l0); split1(v01, h1, l1);
                *(uint32_t*)(outH + (size_t)r * E_ + c) = pack2(h0, h1);
                *(uint32_t*)(outL + (size_t)r * E_ + c) = pack2(l0, l1);
                split1(v10, h0, l0); split1(v11, h1, l1);
                *(uint32_t*)(outH + (size_t)(r + 8) * E_ + c) = pack2(h0, h1);
                *(uint32_t*)(outL + (size_t)(r + 8) * E_ + c) = pack2(l0, l1);
            }
        }
}

// =========================== K^T K / K^T V ========================================
// grid (64 heads, 2): which=0 -> KK, which=1 -> KTV. M=N=128, K=4096.
__global__ __launch_bounds__(256, 1) void ktk_mma()
{
    extern __shared__ char smraw[];
    const uint32_t sm = (smem_u32(smraw) + 127) & ~127u;
    const int tid = threadIdx.x, lane = tid & 31, wid = tid >> 5;
    const int wm = wid >> 2, wn = wid & 3;
    const int head = blockIdx.x, which = blockIdx.y;

    const size_t hb = (size_t)head * HD_ * S_;
    const bf16* pAh = g_Kth + hb;
    const bf16* pAl = g_Ktl + hb;
    const bf16* pBh = (which ? g_Vth : g_Kth) + hb;
    const bf16* pBl = (which ? g_Vtl : g_Ktl) + hb;
    float* out = (which ? g_ktv : g_kk) + (size_t)head * HD_ * HD_;

    float acc[4][4][4];
    #pragma unroll
    for (int a = 0; a < 4; a++)
        #pragma unroll
        for (int b = 0; b < 4; b++)
            #pragma unroll
            for (int c = 0; c < 4; c++) acc[a][b][c] = 0.f;

    run_mainloop(sm, pAh, pAl, S_, pBh, pBl, S_, S_ / 64, wm, wn, lane, tid, acc);

    const int row_base = wm * 64 + (lane >> 2);
    const int col_base = wn * 32 + (lane & 3) * 2;
    #pragma unroll
    for (int mi = 0; mi < 4; mi++)
        #pragma unroll
        for (int nj = 0; nj < 4; nj++) {
            const int r = row_base + mi * 16;
            const int c = col_base + nj * 8;
            *(float2*)(out + (size_t)r * HD_ + c) =
                make_float2(acc[mi][nj][0], acc[mi][nj][1]);
            *(float2*)(out + (size_t)(r + 8) * HD_ + c) =
                make_float2(acc[mi][nj][2], acc[mi][nj][3]);
        }
}

// =========================== solve + softmax (fp32 SIMT) ==========================
#define LDAUG 257
__global__ __launch_bounds__(256) void solve_softmax_kernel(const float* __restrict__ alpha)
{
    extern __shared__ float sAug[];        // [128][LDAUG]
    __shared__ float facs[128];
    const int head = blockIdx.x;
    const int tid = threadIdx.x;
    const float* kk  = g_kk  + (size_t)head * HD_ * HD_;
    const float* ktv = g_ktv + (size_t)head * HD_ * HD_;
    const float a = alpha[0];

    for (int idx = tid; idx < HD_ * HD_; idx += 256) {
        int r = idx >> 7, c = idx & 127;
        sAug[r * LDAUG + c]       = kk[idx] + (r == c ? a : 0.f);
        sAug[r * LDAUG + 128 + c] = ktv[idx];
    }
    __syncthreads();

    for (int k = 0; k < HD_; k++) {
        if (tid < 128) facs[tid] = sAug[tid * LDAUG + k];
        __syncthreads();
        float pivc = sAug[k * LDAUG + tid] / facs[k];
        sAug[k * LDAUG + tid] = pivc;
        __syncthreads();
        #pragma unroll 4
        for (int r = 0; r < HD_; r++)
            if (r != k) sAug[r * LDAUG + tid] -= facs[r] * pivc;
        __syncthreads();
    }

    const int warp = tid >> 5, lane = tid & 31;
    for (int r = warp; r < HD_; r += 8) {
        float vals[4];
        float mx = -1e30f;
        #pragma unroll
        for (int t = 0; t < 4; t++) {
            vals[t] = sAug[r * LDAUG + 128 + lane + 32 * t];
            mx = fmaxf(mx, vals[t]);
        }
        #pragma unroll
        for (int o = 16; o; o >>= 1) mx = fmaxf(mx, __shfl_xor_sync(0xffffffffu, mx, o));
        float sum = 0.f;
        #pragma unroll
        for (int t = 0; t < 4; t++) { vals[t] = expf(vals[t] - mx); sum += vals[t]; }
        #pragma unroll
        for (int o = 16; o; o >>= 1) sum += __shfl_xor_sync(0xffffffffu, sum, o);
        float inv = 1.f / sum;
        #pragma unroll
        for (int t = 0; t < 4; t++) {
            int e = lane + 32 * t;
            float p = vals[t] * inv;
            bf16 h, l; split1(p, h, l);
            g_sTh[(size_t)head * HD_ * HD_ + e * HD_ + r] = h;  // score^T[e][d=r]
            g_sTl[(size_t)head * HD_ * HD_ + e * HD_ + r] = l;
        }
    }
}

// =========================== attn = Q @ score =====================================
// grid (64 heads, 32 s-tiles): D[s(128)][e(128)] = sum_d q[s][d] * scoreT[e][d]; K=128.
__global__ __launch_bounds__(256, 1) void attn_mma()
{
    extern __shared__ char smraw[];
    const uint32_t sm = (smem_u32(smraw) + 127) & ~127u;
    const int tid = threadIdx.x, lane = tid & 31, wid = tid >> 5;
    const int wm = wid >> 2, wn = wid & 3;
    const int head = blockIdx.x, stile = blockIdx.y;
    const int bb = head >> 4, h = head & 15;
    const size_t arow0 = (size_t)(bb * S_ + stile * 128);

    const bf16* pAh = g_qh + arow0 * E_ + h * 128;
    const bf16* pAl = g_ql + arow0 * E_ + h * 128;
    const bf16* pBh = g_sTh + (size_t)head * HD_ * HD_;
    const bf16* pBl = g_sTl + (size_t)head * HD_ * HD_;

    float acc[4][4][4];
    #pragma unroll
    for (int a = 0; a < 4; a++)
        #pragma unroll
        for (int b = 0; b < 4; b++)
            #pragma unroll
            for (int c = 0; c < 4; c++) acc[a][b][c] = 0.f;

    run_mainloop(sm, pAh, pAl, E_, pBh, pBl, HD_, HD_ / 64, wm, wn, lane, tid, acc);

    const int row_base = wm * 64 + (lane >> 2);
    const int col_base = h * 128 + wn * 32 + (lane & 3) * 2;
    #pragma unroll
    for (int mi = 0; mi < 4; mi++)
        #pragma unroll
        for (int nj = 0; nj < 4; nj++) {
            const size_t r = arow0 + row_base + mi * 16;
            const int c = col_base + nj * 8;
            bf16 h0, l0, h1, l1;
            split1(acc[mi][nj][0], h0, l0); split1(acc[mi][nj][1], h1, l1);
            *(uint32_t*)(g_ah + r * E_ + c) = pack2(h0, h1);
            *(uint32_t*)(g_al + r * E_ + c) = pack2(l0, l1);
            split1(acc[mi][nj][2], h0, l0); split1(acc[mi][nj][3], h1, l1);
            *(uint32_t*)(g_ah + (r + 8) * E_ + c) = pack2(h0, h1);
            *(uint32_t*)(g_al + (r + 8) * E_ + c) = pack2(l0, l1);
        }
}

// =================================================================================
extern "C" void kernel_launch(void* const* d_in, const int* in_sizes, int n_in,
                              void* d_out, int out_size)
{
    (void)in_sizes; (void)n_in; (void)out_size;
    const float* x     = (const float*)d_in[0];
    const float* alpha = (const float*)d_in[1];
    const float* Wq    = (const float*)d_in[2];
    const float* bq    = (const float*)d_in[3];
    const float* Wk    = (const float*)d_in[4];
    const float* bk    = (const float*)d_in[5];
    const float* Wv    = (const float*)d_in[6];
    const float* bv    = (const float*)d_in[7];
    const float* Wfc   = (const float*)d_in[8];
    const float* bfc   = (const float*)d_in[9];
    float* out = (float*)d_out;

    bf16 *xh, *xl, *wqh, *wql, *wkh, *wkl, *wvh, *wvl, *wfh, *wfl, *qh, *ql, *ah, *al;
    float *k, *v;
    cudaGetSymbolAddress((void**)&xh, g_xh);   cudaGetSymbolAddress((void**)&xl, g_xl);
    cudaGetSymbolAddress((void**)&wqh, g_wqh); cudaGetSymbolAddress((void**)&wql, g_wql);
    cudaGetSymbolAddress((void**)&wkh, g_wkh); cudaGetSymbolAddress((void**)&wkl, g_wkl);
    cudaGetSymbolAddress((void**)&wvh, g_wvh); cudaGetSymbolAddress((void**)&wvl, g_wvl);
    cudaGetSymbolAddress((void**)&wfh, g_wfh); cudaGetSymbolAddress((void**)&wfl, g_wfl);
    cudaGetSymbolAddress((void**)&qh, g_qh);   cudaGetSymbolAddress((void**)&ql, g_ql);
    cudaGetSymbolAddress((void**)&k, g_k);     cudaGetSymbolAddress((void**)&v, g_v);
    cudaGetSymbolAddress((void**)&ah, g_ah);   cudaGetSymbolAddress((void**)&al, g_al);

    const int SMEM_MMA = 3 * STAGE_BYTES + 1024;  // 197632
    const int SMEM_S   = 128 * LDAUG * 4;         // 131584
    cudaFuncSetAttribute(gemm_big, cudaFuncAttributeMaxDynamicSharedMemorySize, SMEM_MMA);
    cudaFuncSetAttribute(ktk_mma,  cudaFuncAttributeMaxDynamicSharedMemorySize, SMEM_MMA);
    cudaFuncSetAttribute(attn_mma, cudaFuncAttributeMaxDynamicSharedMemorySize, SMEM_MMA);
    cudaFuncSetAttribute(solve_softmax_kernel, cudaFuncAttributeMaxDynamicSharedMemorySize, SMEM_S);

    // 1) split x into bf16 hi/lo
    conv_split_kernel<<<(int)((size_t)MTOT * E_ / 4 / 256), 256>>>(x, xh, xl);
    // 2) transpose+split weights -> [N x K] hi/lo
    dim3 tb(32, 8), tg(E_ / 32, E_ / 32);
    conv_splitT_kernel<<<tg, tb>>>(Wq, wqh, wql);
    conv_splitT_kernel<<<tg, tb>>>(Wk, wkh, wkl);
    conv_splitT_kernel<<<tg, tb>>>(Wv, wvh, wvl);
    conv_splitT_kernel<<<tg, tb>>>(Wfc, wfh, wfl);
    // 3) Q/K/V projections
    dim3 gg(E_ / 128, MTOT / 128);   // (16, 128)
    gemm_big<<<gg, 256, SMEM_MMA>>>(xh, xl, wqh, wql, bq, nullptr, qh, ql);
    gemm_big<<<gg, 256, SMEM_MMA>>>(xh, xl, wkh, wkl, bk, k, nullptr, nullptr);
    gemm_big<<<gg, 256, SMEM_MMA>>>(xh, xl, wvh, wvl, bv, v, nullptr, nullptr);
    // 4) transpose+split K, V to [head*HD + d][s]
    bf16 *Kth, *Ktl, *Vth, *Vtl;
    cudaGetSymbolAddress((void**)&Kth, g_Kth); cudaGetSymbolAddress((void**)&Ktl, g_Ktl);
    cudaGetSymbolAddress((void**)&Vth, g_Vth); cudaGetSymbolAddress((void**)&Vtl, g_Vtl);
    dim3 kg(S_ / 32, E_ / 32, B_);
    transpose_split_kv_kernel<<<kg, tb>>>(k, Kth, Ktl);
    transpose_split_kv_kernel<<<kg, tb>>>(v, Vth, Vtl);
    // 5) K^T K and K^T V
    ktk_mma<<<dim3(NHEADS, 2), 256, SMEM_MMA>>>();
    // 6) solve + softmax -> score^T (bf16 hi/lo)
    solve_softmax_kernel<<<NHEADS, 256, SMEM_S>>>(alpha);
    // 7) attn = Q @ score
    attn_mma<<<dim3(NHEADS, S_ / 128), 256, SMEM_MMA>>>();
    // 8) output projection
    gemm_big<<<gg, 256, SMEM_MMA>>>(ah, al, wfh, wfl, bfc, out, nullptr, nullptr);
}

// round 7
// speedup vs baseline: 2.5513x; 1.0065x over previous
#include <cuda_runtime.h>
#include <cuda_bf16.h>
#include <math.h>
#include <stdint.h>

#define B_   4
#define S_   4096
#define E_   2048
#define NH_  16
#define HD_  128
#define MTOT (B_ * S_)       /* 16384 */
#define NHEADS (B_ * NH_)    /* 64 */
#define KSPLIT 4

typedef __nv_bfloat16 bf16;

// ---------------- scratch (device globals; no runtime allocation) ----------------
__device__ bf16  g_xh [(size_t)MTOT * E_], g_xl [(size_t)MTOT * E_];
__device__ bf16  g_wqh[(size_t)E_ * E_],   g_wql[(size_t)E_ * E_];
__device__ bf16  g_wkh[(size_t)E_ * E_],   g_wkl[(size_t)E_ * E_];
__device__ bf16  g_wvh[(size_t)E_ * E_],   g_wvl[(size_t)E_ * E_];
__device__ bf16  g_wfh[(size_t)E_ * E_],   g_wfl[(size_t)E_ * E_];
__device__ bf16  g_qh [(size_t)MTOT * E_], g_ql [(size_t)MTOT * E_];
__device__ bf16  g_Kth[(size_t)NHEADS * HD_ * S_], g_Ktl[(size_t)NHEADS * HD_ * S_];
__device__ bf16  g_Vth[(size_t)NHEADS * HD_ * S_], g_Vtl[(size_t)NHEADS * HD_ * S_];
__device__ float g_kkp [KSPLIT * NHEADS * HD_ * HD_];
__device__ float g_ktvp[KSPLIT * NHEADS * HD_ * HD_];
__device__ bf16  g_sTh[NHEADS * HD_ * HD_], g_sTl[NHEADS * HD_ * HD_];
__device__ bf16  g_ah [(size_t)MTOT * E_], g_al [(size_t)MTOT * E_];

// =========================== helpers ==============================================
__device__ __forceinline__ uint32_t smem_u32(const void* p) {
    return (uint32_t)__cvta_generic_to_shared(p);
}
__device__ __forceinline__ void split1(float v, bf16& h, bf16& l) {
    h = __float2bfloat16(v);
    l = __float2bfloat16(v - __bfloat162float(h));
}
__device__ __forceinline__ uint32_t pack2(bf16 a, bf16 b) {
    return (uint32_t)__bfloat16_as_ushort(a) | ((uint32_t)__bfloat16_as_ushort(b) << 16);
}

#define CP_COMMIT() asm volatile("cp.async.commit_group;" ::: "memory")
#define CP_WAIT(n)  asm volatile("cp.async.wait_group %0;" :: "n"(n) : "memory")

__device__ __forceinline__ void cpa16(uint32_t s, const void* g) {
    asm volatile("cp.async.cg.shared.global [%0], [%1], 16;" :: "r"(s), "l"(g));
}
__device__ __forceinline__ void ldsm4(uint32_t (&r)[4], uint32_t a) {
    asm volatile("ldmatrix.sync.aligned.m8n8.x4.shared.b16 {%0,%1,%2,%3}, [%4];"
                 : "=r"(r[0]), "=r"(r[1]), "=r"(r[2]), "=r"(r[3]) : "r"(a));
}
__device__ __forceinline__ void mma_bf16(float (&c)[4], const uint32_t (&a)[4],
                                         uint32_t b0, uint32_t b1) {
    asm volatile("mma.sync.aligned.m16n8k16.row.col.f32.bf16.bf16.f32 "
        "{%0,%1,%2,%3}, {%4,%5,%6,%7}, {%8,%9}, {%0,%1,%2,%3};"
        : "+f"(c[0]), "+f"(c[1]), "+f"(c[2]), "+f"(c[3])
        : "r"(a[0]), "r"(a[1]), "r"(a[2]), "r"(a[3]), "r"(b0), "r"(b1));
}

// =========================== mma GEMM machinery ===================================
// Block tile 128x128x64, 8 warps (2 M x 4 N), warp tile 64x32.
// smem tile: 128 rows x 64 bf16 = 128B rows, SW128 XOR-swizzled (conflict-free).
#define TILE_BYTES 16384            /* 128 * 128B */
#define STAGE_BYTES (4 * TILE_BYTES) /* Ah | Al | Bh | Bl = 64KB */

__device__ __forceinline__ uint32_t swz(uint32_t row, uint32_t cb) {
    return row * 128 + (cb ^ ((row & 7) << 4));
}

// load a 128x64 bf16 tile (global row stride ldg halves) into swizzled smem
__device__ __forceinline__ void load_tile64(uint32_t sbase, const bf16* g, int ldg, int tid) {
    #pragma unroll
    for (int t = 0; t < 4; t++) {
        int idx = tid + t * 256;        // 1024 chunks of 16B
        int r = idx >> 3, c = idx & 7;
        cpa16(sbase + swz(r, c * 16), g + (size_t)r * ldg + c * 8);
    }
}
__device__ __forceinline__ void stage_load(uint32_t sbase,
    const bf16* Ah, const bf16* Al, int lda,
    const bf16* Bh, const bf16* Bl, int ldb, int tid)
{
    load_tile64(sbase,                  Ah, lda, tid);
    load_tile64(sbase + TILE_BYTES,     Al, lda, tid);
    load_tile64(sbase + 2 * TILE_BYTES, Bh, ldb, tid);
    load_tile64(sbase + 3 * TILE_BYTES, Bl, ldb, tid);
}

struct Frag { uint32_t ah[4][4], al[4][4], bh[2][4], bl[2][4]; };

__device__ __forceinline__ void load_frag(Frag& f, uint32_t sbase, int kk,
                                          int arow, uint32_t acbx, int brow, uint32_t bcbx)
{
    const uint32_t sAh = sbase, sAl = sbase + TILE_BYTES;
    const uint32_t sBh = sbase + 2 * TILE_BYTES, sBl = sbase + 3 * TILE_BYTES;
    const uint32_t acb = kk * 32 + acbx, bcb = kk * 32 + bcbx;
    #pragma unroll
    for (int mi = 0; mi < 4; mi++) {
        ldsm4(f.ah[mi], sAh + swz(arow + mi * 16, acb));
        ldsm4(f.al[mi], sAl + swz(arow + mi * 16, acb));
    }
    #pragma unroll
    for (int nj2 = 0; nj2 < 2; nj2++) {
        ldsm4(f.bh[nj2], sBh + swz(brow + nj2 * 16, bcb));
        ldsm4(f.bl[nj2], sBl + swz(brow + nj2 * 16, bcb));
    }
}
__device__ __forceinline__ void mma_frag(const Frag& f, float (&acc)[4][4][4]) {
    #pragma unroll
    for (int mi = 0; mi < 4; mi++)
        #pragma unroll
        for (int nj = 0; nj < 4; nj++) {
            const int j2 = nj >> 1, jo = (nj & 1) * 2;
            mma_bf16(acc[mi][nj], f.ah[mi], f.bh[j2][jo], f.bh[j2][jo + 1]);
            mma_bf16(acc[mi][nj], f.ah[mi], f.bl[j2][jo], f.bl[j2][jo + 1]);
            mma_bf16(acc[mi][nj], f.al[mi], f.bh[j2][jo], f.bh[j2][jo + 1]);
        }
}

// consume one 128x128x64 stage: 3 chains, 2-frag software pipeline
__device__ __forceinline__ void compute_stage(uint32_t sbase, int wm, int wn, int lane,
                                              float (&acc)[4][4][4])
{
    const int arow = wm * 64 + (lane & 15);
    const uint32_t acbx = (lane & 16) ? 16 : 0;
    const int brow = wn * 32 + (lane & 7) + ((lane & 16) ? 8 : 0);
    const uint32_t bcbx = (lane & 8) ? 16 : 0;

    Frag f0, f1;
    load_frag(f0, sbase, 0, arow, acbx, brow, bcbx);
    load_frag(f1, sbase, 1, arow, acbx, brow, bcbx);
    mma_frag(f0, acc);
    load_frag(f0, sbase, 2, arow, acbx, brow, bcbx);
    mma_frag(f1, acc);
    load_frag(f1, sbase, 3, arow, acbx, brow, bcbx);
    mma_frag(f0, acc);
    mma_frag(f1, acc);
}

// full pipelined mainloop over KT k-tiles of 64 (KT >= 2), 3-stage (192KB)
__device__ __forceinline__ void run_mainloop(uint32_t sm,
    const bf16* pAh, const bf16* pAl, int lda,
    const bf16* pBh, const bf16* pBl, int ldb, int KT,
    int wm, int wn, int lane, int tid, float (&acc)[4][4][4])
{
    stage_load(sm, pAh, pAl, lda, pBh, pBl, ldb, tid);
    CP_COMMIT();
    stage_load(sm + STAGE_BYTES, pAh + 64, pAl + 64, lda, pBh + 64, pBl + 64, ldb, tid);
    CP_COMMIT();
    for (int i = 0; i < KT; i++) {
        if (i + 2 < KT) { CP_WAIT(1); } else { CP_WAIT(0); }
        __syncthreads();
        if (i + 2 < KT) {
            const int k0 = (i + 2) * 64, slot = (i + 2) % 3;
            stage_load(sm + slot * STAGE_BYTES, pAh + k0, pAl + k0, lda,
                       pBh + k0, pBl + k0, ldb, tid);
            CP_COMMIT();
        }
        compute_stage(sm + (i % 3) * STAGE_BYTES, wm, wn, lane, acc);
    }
}

// =========================== conversion kernels ===================================
__global__ void conv_split_kernel(const float* __restrict__ in, bf16* __restrict__ hi,
                                  bf16* __restrict__ lo) {
    size_t i = ((size_t)blockIdx.x * 256 + threadIdx.x) * 4;
    float4 v = *(const float4*)(in + i);
    bf16 h0, l0, h1, l1, h2, l2, h3, l3;
    split1(v.x, h0, l0); split1(v.y, h1, l1); split1(v.z, h2, l2); split1(v.w, h3, l3);
    *(uint2*)(hi + i) = make_uint2(pack2(h0, h1), pack2(h2, h3));
    *(uint2*)(lo + i) = make_uint2(pack2(l0, l1), pack2(l2, l3));
}

// W[K x N] fp32 -> Wt[N x K] bf16 hi/lo (transpose + split)
__global__ void conv_splitT_kernel(const float* __restrict__ W, bf16* __restrict__ th,
                                   bf16* __restrict__ tl) {
    __shared__ float t[32][33];
    const int n0 = blockIdx.x * 32, k0 = blockIdx.y * 32;
    const int tx = threadIdx.x, ty = threadIdx.y;
    #pragma unroll
    for (int j = 0; j < 4; j++)
        t[ty + 8 * j][tx] = W[(size_t)(k0 + ty + 8 * j) * E_ + n0 + tx];
    __syncthreads();
    #pragma unroll
    for (int j = 0; j < 4; j++) {
        int n = n0 + ty + 8 * j;
        float v = t[tx][ty + 8 * j];
        bf16 h, l; split1(v, h, l);
        th[(size_t)n * E_ + k0 + tx] = h;
        tl[(size_t)n * E_ + k0 + tx] = l;
    }
}

// =========================== fused QKV GEMM =======================================
// z=0: Q -> row-major bf16 hi/lo (g_qh/g_ql)
// z=1: K -> transposed bf16 hi/lo (g_Kth/g_Ktl)   [row b*E+e, col s]
// z=2: V -> transposed bf16 hi/lo (g_Vth/g_Vtl)
__global__ __launch_bounds__(256, 1) void gemm_qkv(
    const float* __restrict__ bq, const float* __restrict__ bk,
    const float* __restrict__ bv)
{
    extern __shared__ char smraw[];
    const uint32_t sm = (smem_u32(smraw) + 127) & ~127u;
    const int tid = threadIdx.x, lane = tid & 31, wid = tid >> 5;
    const int wm = wid >> 2, wn = wid & 3;
    const int m0 = blockIdx.y * 128, n0 = blockIdx.x * 128;
    const int z = blockIdx.z;

    const bf16* Bh = (z == 0) ? g_wqh : (z == 1) ? g_wkh : g_wvh;
    const bf16* Bl = (z == 0) ? g_wql : (z == 1) ? g_wkl : g_wvl;
    const float* bias = (z == 0) ? bq : (z == 1) ? bk : bv;

    float acc[4][4][4];
    #pragma unroll
    for (int a = 0; a < 4; a++)
        #pragma unroll
        for (int b = 0; b < 4; b++)
            #pragma unroll
            for (int c = 0; c < 4; c++) acc[a][b][c] = 0.f;

    run_mainloop(sm, g_xh + (size_t)m0 * E_, g_xl + (size_t)m0 * E_, E_,
                 Bh + (size_t)n0 * E_, Bl + (size_t)n0 * E_, E_, E_ / 64,
                 wm, wn, lane, tid, acc);

    const int rb = wm * 64 + (lane >> 2);
    const int cb = wn * 32 + (lane & 3) * 2;

    if (z == 0) {
        #pragma unroll
        for (int mi = 0; mi < 4; mi++)
            #pragma unroll
            for (int nj = 0; nj < 4; nj++) {
                const int r = m0 + rb + mi * 16;
                const int c = n0 + cb + nj * 8;
                const float b0 = bias[c], b1 = bias[c + 1];
                bf16 h0, l0, h1, l1;
                split1(acc[mi][nj][0] + b0, h0, l0); split1(acc[mi][nj][1] + b1, h1, l1);
                *(uint32_t*)(g_qh + (size_t)r * E_ + c) = pack2(h0, h1);
                *(uint32_t*)(g_ql + (size_t)r * E_ + c) = pack2(l0, l1);
                split1(acc[mi][nj][2] + b0, h0, l0); split1(acc[mi][nj][3] + b1, h1, l1);
                *(uint32_t*)(g_qh + (size_t)(r + 8) * E_ + c) = pack2(h0, h1);
                *(uint32_t*)(g_ql + (size_t)(r + 8) * E_ + c) = pack2(l0, l1);
            }
        return;
    }

    // transposed epilogue via smem bounce (pitch 129 floats)
    __syncthreads();                 // everyone done reading stage smem
    float* sT = (float*)(smraw) + 32;    // reuse dynamic smem (aligned enough: +128B)
    #pragma unroll
    for (int mi = 0; mi < 4; mi++)
        #pragma unroll
        for (int nj = 0; nj < 4; nj++) {
            const int r = rb + mi * 16;
            const int c = cb + nj * 8;
            const float b0 = bias[n0 + c], b1 = bias[n0 + c + 1];
            sT[r * 129 + c]           = acc[mi][nj][0] + b0;
            sT[r * 129 + c + 1]       = acc[mi][nj][1] + b1;
            sT[(r + 8) * 129 + c]     = acc[mi][nj][2] + b0;
            sT[(r + 8) * 129 + c + 1] = acc[mi][nj][3] + b1;
        }
    __syncthreads();

    bf16* th = (z == 1) ? g_Kth : g_Vth;
    bf16* tl = (z == 1) ? g_Ktl : g_Vtl;
    const int e = tid >> 1, sh = (tid & 1) * 64;
    const int bB = m0 / S_, sInB = (m0 % S_) + sh;
    const size_t grow = ((size_t)(bB * E_ + n0 + e)) * S_ + sInB;

    uint32_t hw[32], lw[32];
    #pragma unroll
    for (int q = 0; q < 32; q++) {
        float v0 = sT[(sh + 2 * q) * 129 + e];
        float v1 = sT[(sh + 2 * q + 1) * 129 + e];
        bf16 h0, l0, h1, l1;
        split1(v0, h0, l0); split1(v1, h1, l1);
        hw[q] = pack2(h0, h1); lw[q] = pack2(l0, l1);
    }
    #pragma unroll
    for (int q = 0; q < 8; q++) {
        *(uint4*)(th + grow + q * 8) = make_uint4(hw[q*4], hw[q*4+1], hw[q*4+2], hw[q*4+3]);
        *(uint4*)(tl + grow + q * 8) = make_uint4(lw[q*4], lw[q*4+1], lw[q*4+2], lw[q*4+3]);
    }
}

// =========================== final GEMM ===========================================
__global__ __launch_bounds__(256, 1) void gemm_fc(const float* __restrict__ bias,
                                                  float* __restrict__ outF)
{
    extern __shared__ char smraw[];
    const uint32_t sm = (smem_u32(smraw) + 127) & ~127u;
    const int tid = threadIdx.x, lane = tid & 31, wid = tid >> 5;
    const int wm = wid >> 2, wn = wid & 3;
    const int m0 = blockIdx.y * 128, n0 = blockIdx.x * 128;

    float acc[4][4][4];
    #pragma unroll
    for (int a = 0; a < 4; a++)
        #pragma unroll
        for (int b = 0; b < 4; b++)
            #pragma unroll
            for (int c = 0; c < 4; c++) acc[a][b][c] = 0.f;

    run_mainloop(sm, g_ah + (size_t)m0 * E_, g_al + (size_t)m0 * E_, E_,
                 g_wfh + (size_t)n0 * E_, g_wfl + (size_t)n0 * E_, E_, E_ / 64,
                 wm, wn, lane, tid, acc);

    const int row_base = m0 + wm * 64 + (lane >> 2);
    const int col_base = n0 + wn * 32 + (lane & 3) * 2;
    #pragma unroll
    for (int mi = 0; mi < 4; mi++)
        #pragma unroll
        for (int nj = 0; nj < 4; nj++) {
            const int r = row_base + mi * 16;
            const int c = col_base + nj * 8;
            const float b0 = bias[c], b1 = bias[c + 1];
            *(float2*)(outF + (size_t)r * E_ + c) =
                make_float2(acc[mi][nj][0] + b0, acc[mi][nj][1] + b1);
            *(float2*)(outF + (size_t)(r + 8) * E_ + c) =
                make_float2(acc[mi][nj][2] + b0, acc[mi][nj][3] + b1);
        }
}

// =========================== K^T K / K^T V (split-K x4) ===========================
// grid (64 heads, 2 which, KSPLIT): each block does K=1024 -> partial buffers.
__global__ __launch_bounds__(256, 1) void ktk_mma()
{
    extern __shared__ char smraw[];
    const uint32_t sm = (smem_u32(smraw) + 127) & ~127u;
    const int tid = threadIdx.x, lane = tid & 31, wid = tid >> 5;
    const int wm = wid >> 2, wn = wid & 3;
    const int head = blockIdx.x, which = blockIdx.y, ks = blockIdx.z;

    const size_t hb = (size_t)head * HD_ * S_ + ks * (S_ / KSPLIT);
    const bf16* pAh = g_Kth + hb;
    const bf16* pAl = g_Ktl + hb;
    const bf16* pBh = (which ? g_Vth : g_Kth) + hb;
    const bf16* pBl = (which ? g_Vtl : g_Ktl) + hb;
    float* out = (which ? g_ktvp : g_kkp) + ((size_t)ks * NHEADS + head) * HD_ * HD_;

    float acc[4][4][4];
    #pragma unroll
    for (int a = 0; a < 4; a++)
        #pragma unroll
        for (int b = 0; b < 4; b++)
            #pragma unroll
            for (int c = 0; c < 4; c++) acc[a][b][c] = 0.f;

    run_mainloop(sm, pAh, pAl, S_, pBh, pBl, S_, (S_ / KSPLIT) / 64,
                 wm, wn, lane, tid, acc);

    const int row_base = wm * 64 + (lane >> 2);
    const int col_base = wn * 32 + (lane & 3) * 2;
    #pragma unroll
    for (int mi = 0; mi < 4; mi++)
        #pragma unroll
        for (int nj = 0; nj < 4; nj++) {
            const int r = row_base + mi * 16;
            const int c = col_base + nj * 8;
            *(float2*)(out + (size_t)r * HD_ + c) =
                make_float2(acc[mi][nj][0], acc[mi][nj][1]);
            *(float2*)(out + (size_t)(r + 8) * HD_ + c) =
                make_float2(acc[mi][nj][2], acc[mi][nj][3]);
        }
}

// =========================== solve + softmax (fp32 SIMT) ==========================
#define LDAUG 257
__global__ __launch_bounds__(256) void solve_softmax_kernel(const float* __restrict__ alpha)
{
    extern __shared__ float sAug[];        // [128][LDAUG]
    __shared__ float facs[128];
    const int head = blockIdx.x;
    const int tid = threadIdx.x;
    const size_t hoff = (size_t)head * HD_ * HD_;
    const size_t pstride = (size_t)NHEADS * HD_ * HD_;
    const float a = alpha[0];

    for (int idx = tid; idx < HD_ * HD_; idx += 256) {
        int r = idx >> 7, c = idx & 127;
        float skk  = g_kkp [hoff + idx] + g_kkp [pstride + hoff + idx]
                   + g_kkp [2 * pstride + hoff + idx] + g_kkp [3 * pstride + hoff + idx];
        float sktv = g_ktvp[hoff + idx] + g_ktvp[pstride + hoff + idx]
                   + g_ktvp[2 * pstride + hoff + idx] + g_ktvp[3 * pstride + hoff + idx];
        sAug[r * LDAUG + c]       = skk + (r == c ? a : 0.f);
        sAug[r * LDAUG + 128 + c] = sktv;
    }
    __syncthreads();

    for (int k = 0; k < HD_; k++) {
        if (tid < 128) facs[tid] = sAug[tid * LDAUG + k];
        __syncthreads();
        float pivc = sAug[k * LDAUG + tid] / facs[k];
        sAug[k * LDAUG + tid] = pivc;
        __syncthreads();
        #pragma unroll 4
        for (int r = 0; r < HD_; r++)
            if (r != k) sAug[r * LDAUG + tid] -= facs[r] * pivc;
        __syncthreads();
    }

    const int warp = tid >> 5, lane = tid & 31;
    for (int r = warp; r < HD_; r += 8) {
        float vals[4];
        float mx = -1e30f;
        #pragma unroll
        for (int t = 0; t < 4; t++) {
            vals[t] = sAug[r * LDAUG + 128 + lane + 32 * t];
            mx = fmaxf(mx, vals[t]);
        }
        #pragma unroll
        for (int o = 16; o; o >>= 1) mx = fmaxf(mx, __shfl_xor_sync(0xffffffffu, mx, o));
        float sum = 0.f;
        #pragma unroll
        for (int t = 0; t < 4; t++) { vals[t] = expf(vals[t] - mx); sum += vals[t]; }
        #pragma unroll
        for (int o = 16; o; o >>= 1) sum += __shfl_xor_sync(0xffffffffu, sum, o);
        float inv = 1.f / sum;
        #pragma unroll
        for (int t = 0; t < 4; t++) {
            int e = lane + 32 * t;
            float p = vals[t] * inv;
            bf16 h, l; split1(p, h, l);
            g_sTh[hoff + e * HD_ + r] = h;  // score^T[e][d=r]
            g_sTl[hoff + e * HD_ + r] = l;
        }
    }
}

// =========================== attn = Q @ score =====================================
// grid (64 heads, 32 s-tiles): D[s(128)][e(128)] = sum_d q[s][d] * scoreT[e][d]; K=128.
__global__ __launch_bounds__(256, 1) void attn_mma()
{
    extern __shared__ char smraw[];
    const uint32_t sm = (smem_u32(smraw) + 127) & ~127u;
    const int tid = threadIdx.x, lane = tid & 31, wid = tid >> 5;
    const int wm = wid >> 2, wn = wid & 3;
    const int head = blockIdx.x, stile = blockIdx.y;
    const int bb = head >> 4, h = head & 15;
    const size_t arow0 = (size_t)(bb * S_ + stile * 128);

    const bf16* pAh = g_qh + arow0 * E_ + h * 128;
    const bf16* pAl = g_ql + arow0 * E_ + h * 128;
    const bf16* pBh = g_sTh + (size_t)head * HD_ * HD_;
    const bf16* pBl = g_sTl + (size_t)head * HD_ * HD_;

    float acc[4][4][4];
    #pragma unroll
    for (int a = 0; a < 4; a++)
        #pragma unroll
        for (int b = 0; b < 4; b++)
            #pragma unroll
            for (int c = 0; c < 4; c++) acc[a][b][c] = 0.f;

    run_mainloop(sm, pAh, pAl, E_, pBh, pBl, HD_, HD_ / 64, wm, wn, lane, tid, acc);

    const int row_base = wm * 64 + (lane >> 2);
    const int col_base = h * 128 + wn * 32 + (lane & 3) * 2;
    #pragma unroll
    for (int mi = 0; mi < 4; mi++)
        #pragma unroll
        for (int nj = 0; nj < 4; nj++) {
            const size_t r = arow0 + row_base + mi * 16;
            const int c = col_base + nj * 8;
            bf16 h0, l0, h1, l1;
            split1(acc[mi][nj][0], h0, l0); split1(acc[mi][nj][1], h1, l1);
            *(uint32_t*)(g_ah + r * E_ + c) = pack2(h0, h1);
            *(uint32_t*)(g_al + r * E_ + c) = pack2(l0, l1);
            split1(acc[mi][nj][2], h0, l0); split1(acc[mi][nj][3], h1, l1);
            *(uint32_t*)(g_ah + (r + 8) * E_ + c) = pack2(h0, h1);
            *(uint32_t*)(g_al + (r + 8) * E_ + c) = pack2(l0, l1);
        }
}

// =================================================================================
extern "C" void kernel_launch(void* const* d_in, const int* in_sizes, int n_in,
                              void* d_out, int out_size)
{
    (void)in_sizes; (void)n_in; (void)out_size;
    const float* x     = (const float*)d_in[0];
    const float* alpha = (const float*)d_in[1];
    const float* Wq    = (const float*)d_in[2];
    const float* bq    = (const float*)d_in[3];
    const float* Wk    = (const float*)d_in[4];
    const float* bk    = (const float*)d_in[5];
    const float* Wv    = (const float*)d_in[6];
    const float* bv    = (const float*)d_in[7];
    const float* Wfc   = (const float*)d_in[8];
    const float* bfc   = (const float*)d_in[9];
    float* out = (float*)d_out;

    bf16 *xh, *xl, *wqh, *wql, *wkh, *wkl, *wvh, *wvl, *wfh, *wfl;
    cudaGetSymbolAddress((void**)&xh, g_xh);   cudaGetSymbolAddress((void**)&xl, g_xl);
    cudaGetSymbolAddress((void**)&wqh, g_wqh); cudaGetSymbolAddress((void**)&wql, g_wql);
    cudaGetSymbolAddress((void**)&wkh, g_wkh); cudaGetSymbolAddress((void**)&wkl, g_wkl);
    cudaGetSymbolAddress((void**)&wvh, g_wvh); cudaGetSymbolAddress((void**)&wvl, g_wvl);
    cudaGetSymbolAddress((void**)&wfh, g_wfh); cudaGetSymbolAddress((void**)&wfl, g_wfl);

    const int SMEM_MMA = 3 * STAGE_BYTES + 1024;  // 197632
    const int SMEM_S   = 128 * LDAUG * 4;         // 131584
    cudaFuncSetAttribute(gemm_qkv, cudaFuncAttributeMaxDynamicSharedMemorySize, SMEM_MMA);
    cudaFuncSetAttribute(gemm_fc,  cudaFuncAttributeMaxDynamicSharedMemorySize, SMEM_MMA);
    cudaFuncSetAttribute(ktk_mma,  cudaFuncAttributeMaxDynamicSharedMemorySize, SMEM_MMA);
    cudaFuncSetAttribute(attn_mma, cudaFuncAttributeMaxDynamicSharedMemorySize, SMEM_MMA);
    cudaFuncSetAttribute(solve_softmax_kernel, cudaFuncAttributeMaxDynamicSharedMemorySize, SMEM_S);

    // 1) split x into bf16 hi/lo
    conv_split_kernel<<<(int)((size_t)MTOT * E_ / 4 / 256), 256>>>(x, xh, xl);
    // 2) transpose+split weights -> [N x K] hi/lo
    dim3 tb(32, 8), tg(E_ / 32, E_ / 32);
    conv_splitT_kernel<<<tg, tb>>>(Wq, wqh, wql);
    conv_splitT_kernel<<<tg, tb>>>(Wk, wkh, wkl);
    conv_splitT_kernel<<<tg, tb>>>(Wv, wvh, wvl);
    conv_splitT_kernel<<<tg, tb>>>(Wfc, wfh, wfl);
    // 3) fused Q/K/V projections (K,V written transposed+split directly)
    gemm_qkv<<<dim3(E_ / 128, MTOT / 128, 3), 256, SMEM_MMA>>>(bq, bk, bv);
    // 4) K^T K and K^T V (split-K x4 into partials)
    ktk_mma<<<dim3(NHEADS, 2, KSPLIT), 256, SMEM_MMA>>>();
    // 5) solve + softmax -> score^T (bf16 hi/lo); sums partials on load
    solve_softmax_kernel<<<NHEADS, 256, SMEM_S>>>(alpha);
    // 6) attn = Q @ score
    attn_mma<<<dim3(NHEADS, S_ / 128), 256, SMEM_MMA>>>();
    // 7) output projection
    gemm_fc<<<dim3(E_ / 128, MTOT / 128), 256, SMEM_MMA>>>(bfc, out);
}

// round 8
// speedup vs baseline: 3.5266x; 1.3822x over previous
#include <cuda_runtime.h>
#include <cuda_fp16.h>
#include <math.h>
#include <stdint.h>

#define B_   4
#define S_   4096
#define E_   2048
#define NH_  16
#define HD_  128
#define MTOT (B_ * S_)       /* 16384 */
#define NHEADS (B_ * NH_)    /* 64 */
#define KSPLIT 4

typedef __half h16;

// ---------------- scratch (device globals; no runtime allocation) ----------------
__device__ h16   g_xh [(size_t)MTOT * E_], g_xl [(size_t)MTOT * E_];
__device__ h16   g_wq [(size_t)E_ * E_],   g_wk [(size_t)E_ * E_];
__device__ h16   g_wv [(size_t)E_ * E_],   g_wf [(size_t)E_ * E_];
__device__ h16   g_qh [(size_t)MTOT * E_], g_ql [(size_t)MTOT * E_];
__device__ h16   g_Kth[(size_t)NHEADS * HD_ * S_], g_Ktl[(size_t)NHEADS * HD_ * S_];
__device__ h16   g_Vth[(size_t)NHEADS * HD_ * S_];
__device__ float g_kkp [KSPLIT * NHEADS * HD_ * HD_];
__device__ float g_ktvp[KSPLIT * NHEADS * HD_ * HD_];
__device__ h16   g_sT [NHEADS * HD_ * HD_];
__device__ h16   g_ah [(size_t)MTOT * E_], g_al [(size_t)MTOT * E_];

// =========================== helpers ==============================================
__device__ __forceinline__ uint32_t smem_u32(const void* p) {
    return (uint32_t)__cvta_generic_to_shared(p);
}
__device__ __forceinline__ void split1h(float v, h16& h, h16& l) {
    h = __float2half_rn(v);
    l = __float2half_rn(v - __half2float(h));
}
__device__ __forceinline__ uint32_t pack2h(h16 a, h16 b) {
    return (uint32_t)__half_as_ushort(a) | ((uint32_t)__half_as_ushort(b) << 16);
}

#define CP_COMMIT() asm volatile("cp.async.commit_group;" ::: "memory")
#define CP_WAIT(n)  asm volatile("cp.async.wait_group %0;" :: "n"(n) : "memory")

__device__ __forceinline__ void cpa16(uint32_t s, const void* g) {
    asm volatile("cp.async.cg.shared.global [%0], [%1], 16;" :: "r"(s), "l"(g));
}
__device__ __forceinline__ void ldsm4(uint32_t (&r)[4], uint32_t a) {
    asm volatile("ldmatrix.sync.aligned.m8n8.x4.shared.b16 {%0,%1,%2,%3}, [%4];"
                 : "=r"(r[0]), "=r"(r[1]), "=r"(r[2]), "=r"(r[3]) : "r"(a));
}
__device__ __forceinline__ void mma_f16(float (&c)[4], const uint32_t (&a)[4],
                                        uint32_t b0, uint32_t b1) {
    asm volatile("mma.sync.aligned.m16n8k16.row.col.f32.f16.f16.f32 "
        "{%0,%1,%2,%3}, {%4,%5,%6,%7}, {%8,%9}, {%0,%1,%2,%3};"
        : "+f"(c[0]), "+f"(c[1]), "+f"(c[2]), "+f"(c[3])
        : "r"(a[0]), "r"(a[1]), "r"(a[2]), "r"(a[3]), "r"(b0), "r"(b1));
}

// =========================== mma GEMM machinery ===================================
// Block tile 128x128x64, 8 warps (2 M x 4 N), warp tile 64x32, 2 chains (AhB, AlB).
// smem tile: 128 rows x 64 halfs = 128B rows, SW128 XOR-swizzled.
#define TILE_BYTES 16384             /* 128 * 128B */
#define STAGE_BYTES (3 * TILE_BYTES) /* Ah | Al | B = 48KB */
#define NSTAGE 4

__device__ __forceinline__ uint32_t swz(uint32_t row, uint32_t cb) {
    return row * 128 + (cb ^ ((row & 7) << 4));
}
__device__ __forceinline__ void load_tile64(uint32_t sbase, const h16* g, int ldg, int tid) {
    #pragma unroll
    for (int t = 0; t < 4; t++) {
        int idx = tid + t * 256;
        int r = idx >> 3, c = idx & 7;
        cpa16(sbase + swz(r, c * 16), g + (size_t)r * ldg + c * 8);
    }
}
__device__ __forceinline__ void stage_load(uint32_t sbase,
    const h16* Ah, const h16* Al, int lda, const h16* Bs, int ldb, int tid)
{
    load_tile64(sbase,                  Ah, lda, tid);
    load_tile64(sbase + TILE_BYTES,     Al, lda, tid);
    load_tile64(sbase + 2 * TILE_BYTES, Bs, ldb, tid);
}

// one 128x128x64 stage, 2 chains
__device__ __forceinline__ void compute_stage(uint32_t sbase, int wm, int wn, int lane,
                                              float (&acc)[4][4][4])
{
    const uint32_t sAh = sbase, sAl = sbase + TILE_BYTES, sB = sbase + 2 * TILE_BYTES;
    const int arow = wm * 64 + (lane & 15);
    const uint32_t acbx = (lane & 16) ? 16 : 0;
    const int brow = wn * 32 + (lane & 7) + ((lane & 16) ? 8 : 0);
    const uint32_t bcbx = (lane & 8) ? 16 : 0;

    #pragma unroll
    for (int kk = 0; kk < 4; kk++) {
        const uint32_t acb = kk * 32 + acbx, bcb = kk * 32 + bcbx;
        uint32_t ah[4][4], al[4][4], bb[2][4];
        #pragma unroll
        for (int mi = 0; mi < 4; mi++) {
            ldsm4(ah[mi], sAh + swz(arow + mi * 16, acb));
            ldsm4(al[mi], sAl + swz(arow + mi * 16, acb));
        }
        #pragma unroll
        for (int nj2 = 0; nj2 < 2; nj2++)
            ldsm4(bb[nj2], sB + swz(brow + nj2 * 16, bcb));
        #pragma unroll
        for (int mi = 0; mi < 4; mi++)
            #pragma unroll
            for (int nj = 0; nj < 4; nj++) {
                const int j2 = nj >> 1, jo = (nj & 1) * 2;
                mma_f16(acc[mi][nj], ah[mi], bb[j2][jo], bb[j2][jo + 1]);
                mma_f16(acc[mi][nj], al[mi], bb[j2][jo], bb[j2][jo + 1]);
            }
    }
}

// pipelined mainloop over KT k-tiles of 64, 4-stage (192KB)
__device__ __forceinline__ void run_mainloop(uint32_t sm,
    const h16* pAh, const h16* pAl, int lda, const h16* pB, int ldb, int KT,
    int wm, int wn, int lane, int tid, float (&acc)[4][4][4])
{
    #pragma unroll
    for (int p = 0; p < NSTAGE - 1; p++) {
        if (p < KT)
            stage_load(sm + p * STAGE_BYTES, pAh + p * 64, pAl + p * 64, lda,
                       pB + p * 64, ldb, tid);
        CP_COMMIT();
    }
    for (int i = 0; i < KT; i++) {
        CP_WAIT(2);
        __syncthreads();
        if (i + 3 < KT) {
            const int k0 = (i + 3) * 64, slot = (i + 3) & 3;
            stage_load(sm + slot * STAGE_BYTES, pAh + k0, pAl + k0, lda,
                       pB + k0, ldb, tid);
        }
        CP_COMMIT();
        compute_stage(sm + (i & 3) * STAGE_BYTES, wm, wn, lane, acc);
    }
}

#define ACC_INIT(acc) \
    _Pragma("unroll") for (int a_ = 0; a_ < 4; a_++) \
    _Pragma("unroll") for (int b_ = 0; b_ < 4; b_++) \
    _Pragma("unroll") for (int c_ = 0; c_ < 4; c_++) acc[a_][b_][c_] = 0.f;

// =========================== conversion kernels ===================================
__global__ void conv_split_kernel(const float* __restrict__ in) {
    size_t i = ((size_t)blockIdx.x * 256 + threadIdx.x) * 4;
    float4 v = *(const float4*)(in + i);
    h16 h0, l0, h1, l1, h2, l2, h3, l3;
    split1h(v.x, h0, l0); split1h(v.y, h1, l1);
    split1h(v.z, h2, l2); split1h(v.w, h3, l3);
    *(uint2*)(g_xh + i) = make_uint2(pack2h(h0, h1), pack2h(h2, h3));
    *(uint2*)(g_xl + i) = make_uint2(pack2h(l0, l1), pack2h(l2, l3));
}

// W[K x N] fp32 -> Wt[N x K] fp16 single (transpose); z selects which weight
__global__ void conv_T_kernel(const float* __restrict__ W0, const float* __restrict__ W1,
                              const float* __restrict__ W2, const float* __restrict__ W3) {
    __shared__ float t[32][33];
    const int z = blockIdx.z;
    const float* W = (z == 0) ? W0 : (z == 1) ? W1 : (z == 2) ? W2 : W3;
    h16* wt = (z == 0) ? g_wq : (z == 1) ? g_wk : (z == 2) ? g_wv : g_wf;
    const int n0 = blockIdx.x * 32, k0 = blockIdx.y * 32;
    const int tx = threadIdx.x, ty = threadIdx.y;
    #pragma unroll
    for (int j = 0; j < 4; j++)
        t[ty + 8 * j][tx] = W[(size_t)(k0 + ty + 8 * j) * E_ + n0 + tx];
    __syncthreads();
    #pragma unroll
    for (int j = 0; j < 4; j++)
        wt[(size_t)(n0 + ty + 8 * j) * E_ + k0 + tx] = __float2half_rn(t[tx][ty + 8 * j]);
}

// =========================== fused QKV GEMM =======================================
// z=0: Q -> row-major fp16 hi/lo; z=1: K -> transposed fp16 hi/lo; z=2: V -> transposed fp16
__global__ __launch_bounds__(256, 1) void gemm_qkv(
    const float* __restrict__ bq, const float* __restrict__ bk,
    const float* __restrict__ bv)
{
    extern __shared__ char smraw[];
    const uint32_t sm = (smem_u32(smraw) + 127) & ~127u;
    const int tid = threadIdx.x, lane = tid & 31, wid = tid >> 5;
    const int wm = wid >> 2, wn = wid & 3;
    const int m0 = blockIdx.y * 128, n0 = blockIdx.x * 128;
    const int z = blockIdx.z;

    const h16* Bp = (z == 0) ? g_wq : (z == 1) ? g_wk : g_wv;
    const float* bias = (z == 0) ? bq : (z == 1) ? bk : bv;

    float acc[4][4][4];
    ACC_INIT(acc)

    run_mainloop(sm, g_xh + (size_t)m0 * E_, g_xl + (size_t)m0 * E_, E_,
                 Bp + (size_t)n0 * E_, E_, E_ / 64, wm, wn, lane, tid, acc);

    const int rb = wm * 64 + (lane >> 2);
    const int cb = wn * 32 + (lane & 3) * 2;

    if (z == 0) {
        #pragma unroll
        for (int mi = 0; mi < 4; mi++)
            #pragma unroll
            for (int nj = 0; nj < 4; nj++) {
                const int r = m0 + rb + mi * 16;
                const int c = n0 + cb + nj * 8;
                const float b0 = bias[c], b1 = bias[c + 1];
                h16 h0, l0, h1, l1;
                split1h(acc[mi][nj][0] + b0, h0, l0); split1h(acc[mi][nj][1] + b1, h1, l1);
                *(uint32_t*)(g_qh + (size_t)r * E_ + c) = pack2h(h0, h1);
                *(uint32_t*)(g_ql + (size_t)r * E_ + c) = pack2h(l0, l1);
                split1h(acc[mi][nj][2] + b0, h0, l0); split1h(acc[mi][nj][3] + b1, h1, l1);
                *(uint32_t*)(g_qh + (size_t)(r + 8) * E_ + c) = pack2h(h0, h1);
                *(uint32_t*)(g_ql + (size_t)(r + 8) * E_ + c) = pack2h(l0, l1);
            }
        return;
    }

    // transposed epilogue via smem bounce (pitch 129 floats)
    __syncthreads();
    float* sT = (float*)(smraw) + 32;
    #pragma unroll
    for (int mi = 0; mi < 4; mi++)
        #pragma unroll
        for (int nj = 0; nj < 4; nj++) {
            const int r = rb + mi * 16;
            const int c = cb + nj * 8;
            const float b0 = bias[n0 + c], b1 = bias[n0 + c + 1];
            sT[r * 129 + c]           = acc[mi][nj][0] + b0;
            sT[r * 129 + c + 1]       = acc[mi][nj][1] + b1;
            sT[(r + 8) * 129 + c]     = acc[mi][nj][2] + b0;
            sT[(r + 8) * 129 + c + 1] = acc[mi][nj][3] + b1;
        }
    __syncthreads();

    const int e = tid >> 1, sh = (tid & 1) * 64;
    const int bB = m0 / S_, sInB = (m0 % S_) + sh;
    const size_t grow = ((size_t)(bB * E_ + n0 + e)) * S_ + sInB;

    if (z == 1) {
        uint32_t hw[32], lw[32];
        #pragma unroll
        for (int q = 0; q < 32; q++) {
            float v0 = sT[(sh + 2 * q) * 129 + e];
            float v1 = sT[(sh + 2 * q + 1) * 129 + e];
            h16 h0, l0, h1, l1;
            split1h(v0, h0, l0); split1h(v1, h1, l1);
            hw[q] = pack2h(h0, h1); lw[q] = pack2h(l0, l1);
        }
        #pragma unroll
        for (int q = 0; q < 8; q++) {
            *(uint4*)(g_Kth + grow + q * 8) = make_uint4(hw[q*4], hw[q*4+1], hw[q*4+2], hw[q*4+3]);
            *(uint4*)(g_Ktl + grow + q * 8) = make_uint4(lw[q*4], lw[q*4+1], lw[q*4+2], lw[q*4+3]);
        }
    } else {
        uint32_t hw[32];
        #pragma unroll
        for (int q = 0; q < 32; q++) {
            float v0 = sT[(sh + 2 * q) * 129 + e];
            float v1 = sT[(sh + 2 * q + 1) * 129 + e];
            hw[q] = pack2h(__float2half_rn(v0), __float2half_rn(v1));
        }
        #pragma unroll
        for (int q = 0; q < 8; q++)
            *(uint4*)(g_Vth + grow + q * 8) = make_uint4(hw[q*4], hw[q*4+1], hw[q*4+2], hw[q*4+3]);
    }
}

// =========================== final GEMM ===========================================
__global__ __launch_bounds__(256, 1) void gemm_fc(const float* __restrict__ bias,
                                                  float* __restrict__ outF)
{
    extern __shared__ char smraw[];
    const uint32_t sm = (smem_u32(smraw) + 127) & ~127u;
    const int tid = threadIdx.x, lane = tid & 31, wid = tid >> 5;
    const int wm = wid >> 2, wn = wid & 3;
    const int m0 = blockIdx.y * 128, n0 = blockIdx.x * 128;

    float acc[4][4][4];
    ACC_INIT(acc)

    run_mainloop(sm, g_ah + (size_t)m0 * E_, g_al + (size_t)m0 * E_, E_,
                 g_wf + (size_t)n0 * E_, E_, E_ / 64, wm, wn, lane, tid, acc);

    const int row_base = m0 + wm * 64 + (lane >> 2);
    const int col_base = n0 + wn * 32 + (lane & 3) * 2;
    #pragma unroll
    for (int mi = 0; mi < 4; mi++)
        #pragma unroll
        for (int nj = 0; nj < 4; nj++) {
            const int r = row_base + mi * 16;
            const int c = col_base + nj * 8;
            const float b0 = bias[c], b1 = bias[c + 1];
            *(float2*)(outF + (size_t)r * E_ + c) =
                make_float2(acc[mi][nj][0] + b0, acc[mi][nj][1] + b1);
            *(float2*)(outF + (size_t)(r + 8) * E_ + c) =
                make_float2(acc[mi][nj][2] + b0, acc[mi][nj][3] + b1);
        }
}

// =========================== K^T K / K^T V (split-K x4) ===========================
__global__ __launch_bounds__(256, 1) void ktk_mma()
{
    extern __shared__ char smraw[];
    const uint32_t sm = (smem_u32(smraw) + 127) & ~127u;
    const int tid = threadIdx.x, lane = tid & 31, wid = tid >> 5;
    const int wm = wid >> 2, wn = wid & 3;
    const int head = blockIdx.x, which = blockIdx.y, ks = blockIdx.z;

    const size_t hb = (size_t)head * HD_ * S_ + ks * (S_ / KSPLIT);
    const h16* pAh = g_Kth + hb;
    const h16* pAl = g_Ktl + hb;
    const h16* pB  = (which ? g_Vth : g_Kth) + hb;
    float* out = (which ? g_ktvp : g_kkp) + ((size_t)ks * NHEADS + head) * HD_ * HD_;

    float acc[4][4][4];
    ACC_INIT(acc)

    run_mainloop(sm, pAh, pAl, S_, pB, S_, (S_ / KSPLIT) / 64, wm, wn, lane, tid, acc);

    const int row_base = wm * 64 + (lane >> 2);
    const int col_base = wn * 32 + (lane & 3) * 2;
    #pragma unroll
    for (int mi = 0; mi < 4; mi++)
        #pragma unroll
        for (int nj = 0; nj < 4; nj++) {
            const int r = row_base + mi * 16;
            const int c = col_base + nj * 8;
            *(float2*)(out + (size_t)r * HD_ + c) =
                make_float2(acc[mi][nj][0], acc[mi][nj][1]);
            *(float2*)(out + (size_t)(r + 8) * HD_ + c) =
                make_float2(acc[mi][nj][2], acc[mi][nj][3]);
        }
}

// =========================== solve + softmax (fp32 SIMT) ==========================
#define LDAUG 257
__global__ __launch_bounds__(256) void solve_softmax_kernel(const float* __restrict__ alpha)
{
    extern __shared__ float sAug[];
    __shared__ float facs[128];
    const int head = blockIdx.x;
    const int tid = threadIdx.x;
    const size_t hoff = (size_t)head * HD_ * HD_;
    const size_t pstride = (size_t)NHEADS * HD_ * HD_;
    const float a = alpha[0];

    for (int idx = tid; idx < HD_ * HD_; idx += 256) {
        int r = idx >> 7, c = idx & 127;
        float skk  = g_kkp [hoff + idx] + g_kkp [pstride + hoff + idx]
                   + g_kkp [2 * pstride + hoff + idx] + g_kkp [3 * pstride + hoff + idx];
        float sktv = g_ktvp[hoff + idx] + g_ktvp[pstride + hoff + idx]
                   + g_ktvp[2 * pstride + hoff + idx] + g_ktvp[3 * pstride + hoff + idx];
        sAug[r * LDAUG + c]       = skk + (r == c ? a : 0.f);
        sAug[r * LDAUG + 128 + c] = sktv;
    }
    __syncthreads();

    for (int k = 0; k < HD_; k++) {
        if (tid < 128) facs[tid] = sAug[tid * LDAUG + k];
        __syncthreads();
        float pivc = sAug[k * LDAUG + tid] / facs[k];
        sAug[k * LDAUG + tid] = pivc;
        __syncthreads();
        #pragma unroll 4
        for (int r = 0; r < HD_; r++)
            if (r != k) sAug[r * LDAUG + tid] -= facs[r] * pivc;
        __syncthreads();
    }

    const int warp = tid >> 5, lane = tid & 31;
    for (int r = warp; r < HD_; r += 8) {
        float vals[4];
        float mx = -1e30f;
        #pragma unroll
        for (int t = 0; t < 4; t++) {
            vals[t] = sAug[r * LDAUG + 128 + lane + 32 * t];
            mx = fmaxf(mx, vals[t]);
        }
        #pragma unroll
        for (int o = 16; o; o >>= 1) mx = fmaxf(mx, __shfl_xor_sync(0xffffffffu, mx, o));
        float sum = 0.f;
        #pragma unroll
        for (int t = 0; t < 4; t++) { vals[t] = expf(vals[t] - mx); sum += vals[t]; }
        #pragma unroll
        for (int o = 16; o; o >>= 1) sum += __shfl_xor_sync(0xffffffffu, sum, o);
        float inv = 1.f / sum;
        #pragma unroll
        for (int t = 0; t < 4; t++) {
            int e = lane + 32 * t;
            g_sT[hoff + e * HD_ + r] = __float2half_rn(vals[t] * inv);  // score^T[e][d=r]
        }
    }
}

// =========================== attn = Q @ score =====================================
__global__ __launch_bounds__(256, 1) void attn_mma()
{
    extern __shared__ char smraw[];
    const uint32_t sm = (smem_u32(smraw) + 127) & ~127u;
    const int tid = threadIdx.x, lane = tid & 31, wid = tid >> 5;
    const int wm = wid >> 2, wn = wid & 3;
    const int head = blockIdx.x, stile = blockIdx.y;
    const int bb = head >> 4, h = head & 15;
    const size_t arow0 = (size_t)(bb * S_ + stile * 128);

    const h16* pAh = g_qh + arow0 * E_ + h * 128;
    const h16* pAl = g_ql + arow0 * E_ + h * 128;
    const h16* pB  = g_sT + (size_t)head * HD_ * HD_;

    float acc[4][4][4];
    ACC_INIT(acc)

    run_mainloop(sm, pAh, pAl, E_, pB, HD_, HD_ / 64, wm, wn, lane, tid, acc);

    const int row_base = wm * 64 + (lane >> 2);
    const int col_base = h * 128 + wn * 32 + (lane & 3) * 2;
    #pragma unroll
    for (int mi = 0; mi < 4; mi++)
        #pragma unroll
        for (int nj = 0; nj < 4; nj++) {
            const size_t r = arow0 + row_base + mi * 16;
            const int c = col_base + nj * 8;
            h16 h0, l0, h1, l1;
            split1h(acc[mi][nj][0], h0, l0); split1h(acc[mi][nj][1], h1, l1);
            *(uint32_t*)(g_ah + r * E_ + c) = pack2h(h0, h1);
            *(uint32_t*)(g_al + r * E_ + c) = pack2h(l0, l1);
            split1h(acc[mi][nj][2], h0, l0); split1h(acc[mi][nj][3], h1, l1);
            *(uint32_t*)(g_ah + (r + 8) * E_ + c) = pack2h(h0, h1);
            *(uint32_t*)(g_al + (r + 8) * E_ + c) = pack2h(l0, l1);
        }
}

// =================================================================================
extern "C" void kernel_launch(void* const* d_in, const int* in_sizes, int n_in,
                              void* d_out, int out_size)
{
    (void)in_sizes; (void)n_in; (void)out_size;
    const float* x     = (const float*)d_in[0];
    const float* alpha = (const float*)d_in[1];
    const float* Wq    = (const float*)d_in[2];
    const float* bq    = (const float*)d_in[3];
    const float* Wk    = (const float*)d_in[4];
    const float* bk    = (const float*)d_in[5];
    const float* Wv    = (const float*)d_in[6];
    const float* bv    = (const float*)d_in[7];
    const float* Wfc   = (const float*)d_in[8];
    const float* bfc   = (const float*)d_in[9];
    float* out = (float*)d_out;

    const int SMEM_MMA = NSTAGE * STAGE_BYTES + 1024;  // 197632
    const int SMEM_S   = 128 * LDAUG * 4;              // 131584
    cudaFuncSetAttribute(gemm_qkv, cudaFuncAttributeMaxDynamicSharedMemorySize, SMEM_MMA);
    cudaFuncSetAttribute(gemm_fc,  cudaFuncAttributeMaxDynamicSharedMemorySize, SMEM_MMA);
    cudaFuncSetAttribute(ktk_mma,  cudaFuncAttributeMaxDynamicSharedMemorySize, SMEM_MMA);
    cudaFuncSetAttribute(attn_mma, cudaFuncAttributeMaxDynamicSharedMemorySize, SMEM_MMA);
    cudaFuncSetAttribute(solve_softmax_kernel, cudaFuncAttributeMaxDynamicSharedMemorySize, SMEM_S);

    // 1) split x into fp16 hi/lo
    conv_split_kernel<<<(int)((size_t)MTOT * E_ / 4 / 256), 256>>>(x);
    // 2) transpose weights -> [N x K] fp16 single (all 4 in one launch)
    dim3 tb(32, 8), tg(E_ / 32, E_ / 32, 4);
    conv_T_kernel<<<tg, tb>>>(Wq, Wk, Wv, Wfc);
    // 3) fused Q/K/V projections (K,V written transposed directly)
    gemm_qkv<<<dim3(E_ / 128, MTOT / 128, 3), 256, SMEM_MMA>>>(bq, bk, bv);
    // 4) K^T K and K^T V (split-K x4 into partials)
    ktk_mma<<<dim3(NHEADS, 2, KSPLIT), 256, SMEM_MMA>>>();
    // 5) solve + softmax -> score^T fp16; sums partials on load
    solve_softmax_kernel<<<NHEADS, 256, SMEM_S>>>(alpha);
    // 6) attn = Q @ score
    attn_mma<<<dim3(NHEADS, S_ / 128), 256, SMEM_MMA>>>();
    // 7) output projection
    gemm_fc<<<dim3(E_ / 128, MTOT / 128), 256, SMEM_MMA>>>(bfc, out);
}